// round 1
// baseline (speedup 1.0000x reference)
#include <cuda_runtime.h>
#include <cuda_bf16.h>

// ---------------------------------------------------------------------------
// Problem constants
// ---------------------------------------------------------------------------
#define S_   7
#define BATCH 8192
#define D_   1024
#define E_   256
#define H_   512
#define SH_  256
#define V_   100
#define D0_  (D_ + E_)     // 1280
#define H4_  (4 * H_)      // 2048

// ---------------------------------------------------------------------------
// Device scratch (static globals; no runtime allocation allowed)
// ---------------------------------------------------------------------------
__device__ float g_P_ih0 [S_ * BATCH * H4_];   // precomputed inputs@W_ih0[:, :D] + b_ih0 + b_hh0
__device__ float g_P_hwN0[S_ * BATCH * H_];    // precomputed inputs@hwN_W0[:, :D] + hwN_b0
__device__ float g_P_hwL0[S_ * BATCH * H_];    // precomputed inputs@hwL_W0[:, :D]
__device__ float g_Wcat0 [S_ * H4_ * (E_ + H_)]; // [W_ih0 emb cols | W_hh0]  (4H x 768)
__device__ float g_Wcat1 [S_ * H4_ * (2 * H_)];  // [W_ih1 | W_hh1]           (4H x 1024)
__device__ float g_bias0 [S_ * H4_];
__device__ float g_bias1 [S_ * H4_];
__device__ float g_cat0  [BATCH * (E_ + H_)];    // [cur_emb | h0]
__device__ float g_cat1  [BATCH * (2 * H_)];     // [cur | h1_prev]
__device__ float g_gates [BATCH * H4_];
__device__ float g_h0[BATCH * H_], g_c0[BATCH * H_];
__device__ float g_h1[BATCH * H_], g_c1[BATCH * H_];
__device__ float g_gateN[BATCH * H_], g_lin[BATCH * H_];
__device__ float g_hidden[BATCH * SH_];

// ---------------------------------------------------------------------------
// Setup: pack weights, fold biases, zero recurrent state
// ---------------------------------------------------------------------------
__global__ void setup_kernel(const float* __restrict__ W_ih0, const float* __restrict__ W_hh0,
                             const float* __restrict__ b_ih0, const float* __restrict__ b_hh0,
                             const float* __restrict__ W_ih1, const float* __restrict__ W_hh1,
                             const float* __restrict__ b_ih1, const float* __restrict__ b_hh1)
{
    const int stride = gridDim.x * blockDim.x;
    int idx = blockIdx.x * blockDim.x + threadIdx.x;

    const int KC0 = E_ + H_;        // 768
    const int KC1 = 2 * H_;         // 1024
    const int total0 = S_ * H4_ * KC0;
    const int total1 = S_ * H4_ * KC1;

    for (int t = idx; t < total0; t += stride) {
        int k = t % KC0;
        int n = (t / KC0) % H4_;
        int s = t / (KC0 * H4_);
        float v;
        if (k < E_) v = W_ih0[((long)s * H4_ + n) * D0_ + D_ + k];
        else        v = W_hh0[((long)s * H4_ + n) * H_ + (k - E_)];
        g_Wcat0[t] = v;
    }
    for (int t = idx; t < total1; t += stride) {
        int k = t % KC1;
        int n = (t / KC1) % H4_;
        int s = t / (KC1 * H4_);
        float v;
        if (k < H_) v = W_ih1[((long)s * H4_ + n) * H_ + k];
        else        v = W_hh1[((long)s * H4_ + n) * H_ + (k - H_)];
        g_Wcat1[t] = v;
    }
    for (int t = idx; t < S_ * H4_; t += stride) {
        g_bias0[t] = b_ih0[t] + b_hh0[t];
        g_bias1[t] = b_ih1[t] + b_hh1[t];
    }
    for (int t = idx; t < BATCH * H_; t += stride) {
        g_h0[t] = 0.f; g_c0[t] = 0.f; g_h1[t] = 0.f; g_c1[t] = 0.f;
    }
}

// ---------------------------------------------------------------------------
// Generic NT GEMM:  C[m,n] = sum_k A[m,k]*B[n,k] (+bias[n]) (+Cin[m,n]) (relu?)
// A: [M,K] row-major (lda), B: [N,K] row-major (ldb), C: [M,N] (ldc)
// Requirements: M % 128 == 0, K % 16 == 0. N guarded.
// blockIdx.z batches with the given strides.
// ---------------------------------------------------------------------------
#define BM 128
#define BN 128
#define BKK 16

__global__ __launch_bounds__(256)
void gemm_nt(const float* __restrict__ A, int lda, long strA,
             const float* __restrict__ Bw, int ldb, long strB,
             float* __restrict__ C, int ldc, long strC,
             const float* __restrict__ Cin, long strCin,
             const float* __restrict__ bias, long strBias,
             int M, int N, int K, int act)
{
    const int z = blockIdx.z;
    A  += z * strA;
    Bw += z * strB;
    C  += z * strC;
    if (Cin)  Cin  += z * strCin;
    if (bias) bias += z * strBias;

    __shared__ float As[BKK][BM + 4];
    __shared__ float Bs[BKK][BN + 4];

    const int tid = threadIdx.x;
    const int tx = tid % 16;          // n direction
    const int ty = tid / 16;          // m direction
    const int m0 = blockIdx.y * BM;
    const int n0 = blockIdx.x * BN;

    const int lRow = tid >> 2;        // 0..63
    const int lCol = (tid & 3) * 4;   // 0,4,8,12

    float acc[8][8];
#pragma unroll
    for (int i = 0; i < 8; ++i)
#pragma unroll
        for (int j = 0; j < 8; ++j) acc[i][j] = 0.f;

    for (int k0 = 0; k0 < K; k0 += BKK) {
#pragma unroll
        for (int r = 0; r < 2; ++r) {
            int row = lRow + r * 64;
            const float4 av = *reinterpret_cast<const float4*>(
                &A[(long)(m0 + row) * lda + k0 + lCol]);
            As[lCol + 0][row] = av.x;
            As[lCol + 1][row] = av.y;
            As[lCol + 2][row] = av.z;
            As[lCol + 3][row] = av.w;
        }
#pragma unroll
        for (int r = 0; r < 2; ++r) {
            int row = lRow + r * 64;  // n index within tile
            float4 bv = make_float4(0.f, 0.f, 0.f, 0.f);
            if (n0 + row < N)
                bv = *reinterpret_cast<const float4*>(
                    &Bw[(long)(n0 + row) * ldb + k0 + lCol]);
            Bs[lCol + 0][row] = bv.x;
            Bs[lCol + 1][row] = bv.y;
            Bs[lCol + 2][row] = bv.z;
            Bs[lCol + 3][row] = bv.w;
        }
        __syncthreads();
#pragma unroll
        for (int k = 0; k < BKK; ++k) {
            float ra[8], rb[8];
#pragma unroll
            for (int i = 0; i < 8; ++i) ra[i] = As[k][ty * 8 + i];
#pragma unroll
            for (int j = 0; j < 8; ++j) rb[j] = Bs[k][tx * 8 + j];
#pragma unroll
            for (int i = 0; i < 8; ++i)
#pragma unroll
                for (int j = 0; j < 8; ++j)
                    acc[i][j] += ra[i] * rb[j];
        }
        __syncthreads();
    }

#pragma unroll
    for (int i = 0; i < 8; ++i) {
        const int m = m0 + ty * 8 + i;
#pragma unroll
        for (int j = 0; j < 8; ++j) {
            const int n = n0 + tx * 8 + j;
            if (n < N) {
                float v = acc[i][j];
                if (bias) v += bias[n];
                if (Cin)  v += Cin[(long)m * ldc + n];
                if (act == 1) v = fmaxf(v, 0.f);
                C[(long)m * ldc + n] = v;
            }
        }
    }
}

// ---------------------------------------------------------------------------
// Elementwise kernels
// ---------------------------------------------------------------------------
__device__ __forceinline__ float sigm(float x) { return 1.f / (1.f + expf(-x)); }

// cat0 = [cur_emb | h0_prev]; slot 0 uses `start`, else teacher-forced embedding
__global__ void build_cat0(const float* __restrict__ start,
                           const float* __restrict__ emb,
                           const int*   __restrict__ labels,
                           int s)
{
    int idx = blockIdx.x * blockDim.x + threadIdx.x;
    const int total = BATCH * (E_ + H_);
    if (idx >= total) return;
    int b = idx / (E_ + H_);
    int c = idx % (E_ + H_);
    float v;
    if (c < E_) {
        if (s == 0) v = start[c];
        else {
            int lab = labels[(s - 1) * BATCH + b];
            v = emb[((long)(s - 1) * V_ + lab) * E_ + c];
        }
    } else {
        v = g_h0[b * H_ + (c - E_)];
    }
    g_cat0[idx] = v;
}

// LSTM cell pointwise update. Optionally mirror h into a concat buffer slice.
__global__ void lstm_ew(const float* __restrict__ gates,
                        float* __restrict__ h, float* __restrict__ c,
                        float* __restrict__ cat_h, int catLd, int catOff)
{
    int idx = blockIdx.x * blockDim.x + threadIdx.x;
    if (idx >= BATCH * H_) return;
    int b = idx / H_;
    int j = idx % H_;
    const float* g = gates + (long)b * H4_;
    float ig = sigm(g[j]);
    float fg = sigm(g[H_ + j]);
    float gg = tanhf(g[2 * H_ + j]);
    float og = sigm(g[3 * H_ + j]);
    float cn = fg * c[idx] + ig * gg;
    float hn = og * tanhf(cn);
    c[idx] = cn;
    h[idx] = hn;
    if (cat_h) cat_h[(long)b * catLd + catOff + j] = hn;
}

// Highway combine for layer 0; also assembles cat1 = [cur | h1_prev]
__global__ void hwy_ew()
{
    int idx = blockIdx.x * blockDim.x + threadIdx.x;
    if (idx >= BATCH * H_) return;
    int b = idx / H_;
    int j = idx % H_;
    float gg  = sigm(g_gateN[idx]);
    float cur = gg * g_h0[idx] + (1.f - gg) * g_lin[idx];
    g_cat1[(long)b * (2 * H_) + j]      = cur;
    g_cat1[(long)b * (2 * H_) + H_ + j] = g_h1[idx];  // h1 from previous slot
}

// ---------------------------------------------------------------------------
// Launch
// ---------------------------------------------------------------------------
static inline void launch_gemm(const float* A, int lda, long sA,
                               const float* Bw, int ldb, long sB,
                               float* C, int ldc, long sC,
                               const float* Cin, long sCin,
                               const float* bias, long sBias,
                               int M, int N, int K, int act, int Z)
{
    dim3 grid((N + BN - 1) / BN, M / BM, Z);
    gemm_nt<<<grid, 256>>>(A, lda, sA, Bw, ldb, sB, C, ldc, sC,
                           Cin, sCin, bias, sBias, M, N, K, act);
}

extern "C" void kernel_launch(void* const* d_in, const int* in_sizes, int n_in,
                              void* d_out, int out_size)
{
    const float* inputs = (const float*)d_in[0];
    const int*   labels = (const int*)  d_in[1];
    const float* start  = (const float*)d_in[2];
    const float* emb    = (const float*)d_in[3];
    const float* W_ih0  = (const float*)d_in[4];
    const float* W_hh0  = (const float*)d_in[5];
    const float* b_ih0  = (const float*)d_in[6];
    const float* b_hh0  = (const float*)d_in[7];
    const float* hwN_W0 = (const float*)d_in[8];
    const float* hwN_b0 = (const float*)d_in[9];
    const float* hwL_W0 = (const float*)d_in[10];
    const float* W_ih1  = (const float*)d_in[11];
    const float* W_hh1  = (const float*)d_in[12];
    const float* b_ih1  = (const float*)d_in[13];
    const float* b_hh1  = (const float*)d_in[14];
    // d_in[15..17] = hwN_W1 / hwN_b1 / hwL_W1: dead in the reference, skipped.
    const float* sh_W   = (const float*)d_in[18];
    const float* sh_b   = (const float*)d_in[19];
    const float* pred_W = (const float*)d_in[20];
    const float* pred_b = (const float*)d_in[21];
    float* out = (float*)d_out;

    // Resolve device-global addresses
    float *P_ih0, *P_hwN0, *P_hwL0, *Wcat0, *Wcat1, *bias0, *bias1;
    float *cat0, *cat1, *gates, *h0, *c0, *h1, *c1, *gateN, *lin, *hidden;
    cudaGetSymbolAddress((void**)&P_ih0,  g_P_ih0);
    cudaGetSymbolAddress((void**)&P_hwN0, g_P_hwN0);
    cudaGetSymbolAddress((void**)&P_hwL0, g_P_hwL0);
    cudaGetSymbolAddress((void**)&Wcat0,  g_Wcat0);
    cudaGetSymbolAddress((void**)&Wcat1,  g_Wcat1);
    cudaGetSymbolAddress((void**)&bias0,  g_bias0);
    cudaGetSymbolAddress((void**)&bias1,  g_bias1);
    cudaGetSymbolAddress((void**)&cat0,   g_cat0);
    cudaGetSymbolAddress((void**)&cat1,   g_cat1);
    cudaGetSymbolAddress((void**)&gates,  g_gates);
    cudaGetSymbolAddress((void**)&h0,     g_h0);
    cudaGetSymbolAddress((void**)&c0,     g_c0);
    cudaGetSymbolAddress((void**)&h1,     g_h1);
    cudaGetSymbolAddress((void**)&c1,     g_c1);
    cudaGetSymbolAddress((void**)&gateN,  g_gateN);
    cudaGetSymbolAddress((void**)&lin,    g_lin);
    cudaGetSymbolAddress((void**)&hidden, g_hidden);

    // 1) pack weights / fold biases / zero state
    setup_kernel<<<2048, 256>>>(W_ih0, W_hh0, b_ih0, b_hh0, W_ih1, W_hh1, b_ih1, b_hh1);

    // 2) slot-parallel precompute of all inputs-dependent partials (grid.z = S)
    // P_ih0[s]  = inputs @ W_ih0[s][:, :D].T + (b_ih0[s] + b_hh0[s])
    launch_gemm(inputs, D_, 0,
                W_ih0, D0_, (long)H4_ * D0_,
                P_ih0, H4_, (long)BATCH * H4_,
                nullptr, 0,
                bias0, H4_,
                BATCH, H4_, D_, 0, S_);
    // P_hwN0[s] = inputs @ hwN_W0[s][:, :D].T + hwN_b0[s]
    launch_gemm(inputs, D_, 0,
                hwN_W0, D0_ + H_, (long)H_ * (D0_ + H_),
                P_hwN0, H_, (long)BATCH * H_,
                nullptr, 0,
                hwN_b0, H_,
                BATCH, H_, D_, 0, S_);
    // P_hwL0[s] = inputs @ hwL_W0[s][:, :D].T
    launch_gemm(inputs, D_, 0,
                hwL_W0, D0_, (long)H_ * D0_,
                P_hwL0, H_, (long)BATCH * H_,
                nullptr, 0,
                nullptr, 0,
                BATCH, H_, D_, 0, S_);

    const int ewBlocks  = (BATCH * H_ + 255) / 256;
    const int catBlocks = (BATCH * (E_ + H_) + 255) / 256;

    // 3) sequential slots
    for (int s = 0; s < S_; ++s) {
        // cat0 = [cur_emb | h0_prev]
        build_cat0<<<catBlocks, 256>>>(start, emb, labels, s);

        // gates0 = cat0 @ [W_ih0_emb | W_hh0].T + P_ih0[s]
        launch_gemm(cat0, E_ + H_, 0,
                    Wcat0 + (long)s * H4_ * (E_ + H_), E_ + H_, 0,
                    gates, H4_, 0,
                    P_ih0 + (long)s * BATCH * H4_, 0,
                    nullptr, 0,
                    BATCH, H4_, E_ + H_, 0, 1);

        // layer-0 LSTM pointwise; mirrors new h0 into cat0[:, E:]
        lstm_ew<<<ewBlocks, 256>>>(gates, h0, c0, cat0, E_ + H_, E_);

        // highway gate pre-activation: cat0 @ hwN_W0[s][:, D:].T + P_hwN0[s]
        launch_gemm(cat0, E_ + H_, 0,
                    hwN_W0 + (long)s * H_ * (D0_ + H_) + D_, D0_ + H_, 0,
                    gateN, H_, 0,
                    P_hwN0 + (long)s * BATCH * H_, 0,
                    nullptr, 0,
                    BATCH, H_, E_ + H_, 0, 1);

        // highway linear: cur_emb @ hwL_W0[s][:, D:].T + P_hwL0[s]   (K = E only)
        launch_gemm(cat0, E_ + H_, 0,
                    hwL_W0 + (long)s * H_ * D0_ + D_, D0_, 0,
                    lin, H_, 0,
                    P_hwL0 + (long)s * BATCH * H_, 0,
                    nullptr, 0,
                    BATCH, H_, E_, 0, 1);

        // cur = sig(gateN)*h0 + (1-sig)*lin ; cat1 = [cur | h1_prev]
        hwy_ew<<<ewBlocks, 256>>>();

        // gates1 = cat1 @ [W_ih1 | W_hh1].T + (b_ih1 + b_hh1)
        launch_gemm(cat1, 2 * H_, 0,
                    Wcat1 + (long)s * H4_ * (2 * H_), 2 * H_, 0,
                    gates, H4_, 0,
                    nullptr, 0,
                    bias1 + (long)s * H4_, 0,
                    BATCH, H4_, 2 * H_, 0, 1);

        // layer-1 LSTM pointwise
        lstm_ew<<<ewBlocks, 256>>>(gates, h1, c1, nullptr, 0, 0);

        // hidden = relu(h1 @ sh_W[s].T + sh_b[s])
        launch_gemm(h1, H_, 0,
                    sh_W + (long)s * SH_ * H_, H_, 0,
                    hidden, SH_, 0,
                    nullptr, 0,
                    sh_b + (long)s * SH_, 0,
                    BATCH, SH_, H_, 1, 1);

        // logits[s] = hidden @ pred_W[s].T + pred_b[s]
        launch_gemm(hidden, SH_, 0,
                    pred_W + (long)s * V_ * SH_, SH_, 0,
                    out + (long)s * BATCH * V_, V_, 0,
                    nullptr, 0,
                    pred_b + (long)s * V_, 0,
                    BATCH, V_, SH_, 0, 1);
    }
}

// round 2
// speedup vs baseline: 1.8697x; 1.8697x over previous
#include <cuda_runtime.h>
#include <cuda_bf16.h>
#include <cstdint>

// ---------------------------------------------------------------------------
// Problem constants
// ---------------------------------------------------------------------------
#define S_   7
#define BATCH 8192
#define D_   1024
#define E_   256
#define H_   512
#define SH_  256
#define V_   100
#define D0_  (D_ + E_)     // 1280
#define H4_  (4 * H_)      // 2048

typedef __nv_bfloat16 bf16;

// ---------------------------------------------------------------------------
// Device scratch (static globals; no runtime allocation allowed)
// ---------------------------------------------------------------------------
// fp32 precomputed partials (Cin epilogue operands)
__device__ float g_P_ih0[S_ * BATCH * H4_];
__device__ float g_P_N  [S_ * BATCH * H_];
__device__ float g_P_L  [S_ * BATCH * H_];
// bf16 hi/lo weights (packed layouts, row-major, K contiguous)
__device__ bf16 g_Wcat0_h[S_ * H4_ * 768],  g_Wcat0_l[S_ * H4_ * 768];   // [Wih0_emb|Whh0]
__device__ bf16 g_Wcat1_h[S_ * H4_ * 1024], g_Wcat1_l[S_ * H4_ * 1024];  // [Wih1|Whh1]
__device__ bf16 g_WihD_h[S_ * H4_ * 1024],  g_WihD_l[S_ * H4_ * 1024];   // W_ih0[:, :D]
__device__ bf16 g_WND_h[S_ * H_ * 1024],    g_WND_l[S_ * H_ * 1024];     // hwN_W0[:, :D]
__device__ bf16 g_WLD_h[S_ * H_ * 1024],    g_WLD_l[S_ * H_ * 1024];     // hwL_W0[:, :D]
__device__ bf16 g_WNE_h[S_ * H_ * 768],     g_WNE_l[S_ * H_ * 768];      // hwN_W0[:, D:]
__device__ bf16 g_WLE_h[S_ * H_ * 256],     g_WLE_l[S_ * H_ * 256];      // hwL_W0[:, D:]
__device__ bf16 g_SHW_h[S_ * SH_ * H_],     g_SHW_l[S_ * SH_ * H_];
__device__ bf16 g_PW_h [S_ * V_ * SH_],     g_PW_l [S_ * V_ * SH_];
__device__ bf16 g_INP_h[BATCH * D_],        g_INP_l[BATCH * D_];
// bf16 hi/lo activations
__device__ bf16 g_cat0_h[BATCH * 768],  g_cat0_l[BATCH * 768];   // [emb | h0]
__device__ bf16 g_cat1_h[BATCH * 1024], g_cat1_l[BATCH * 1024];  // [cur | h1]
__device__ bf16 g_hid_h[BATCH * SH_],   g_hid_l[BATCH * SH_];
// fp32 state / temporaries
__device__ float g_gates[BATCH * H4_];
__device__ float g_gateN[BATCH * H_], g_lin[BATCH * H_];
__device__ float g_h0[BATCH * H_], g_c0[BATCH * H_], g_c1[BATCH * H_];
__device__ float g_bias0[S_ * H4_], g_bias1[S_ * H4_];

// ---------------------------------------------------------------------------
// Helpers
// ---------------------------------------------------------------------------
__device__ __forceinline__ void bsplit(float v, bf16* hp, bf16* lp) {
    bf16 h = __float2bfloat16(v);
    *hp = h;
    *lp = __float2bfloat16(v - __bfloat162float(h));
}
__device__ __forceinline__ float sigm(float x) { return 1.f / (1.f + expf(-x)); }

// ---------------------------------------------------------------------------
// Weight slice conversion: dst[r*dstStride + dstOff + c] = split(src[r*srcStride + srcOff + c])
// ---------------------------------------------------------------------------
__global__ void conv_slice(const float* __restrict__ src, long srcStride, long srcOff,
                           bf16* __restrict__ hi, bf16* __restrict__ lo,
                           long dstStride, long dstOff,
                           long rows, int cols)
{
    long total = rows * cols;
    long stride = (long)gridDim.x * blockDim.x;
    for (long t = blockIdx.x * (long)blockDim.x + threadIdx.x; t < total; t += stride) {
        long r = t / cols;
        int  c = (int)(t % cols);
        float v = src[r * srcStride + srcOff + c];
        long di = r * dstStride + dstOff + c;
        bsplit(v, hi + di, lo + di);
    }
}

// Misc init: fold biases, zero states and stale activation slices
__global__ void misc_init(const float* __restrict__ b_ih0, const float* __restrict__ b_hh0,
                          const float* __restrict__ b_ih1, const float* __restrict__ b_hh1)
{
    long stride = (long)gridDim.x * blockDim.x;
    for (long t = blockIdx.x * (long)blockDim.x + threadIdx.x; t < S_ * H4_; t += stride) {
        g_bias0[t] = b_ih0[t] + b_hh0[t];
        g_bias1[t] = b_ih1[t] + b_hh1[t];
    }
    bf16 z = __float2bfloat16(0.f);
    for (long t = blockIdx.x * (long)blockDim.x + threadIdx.x; t < (long)BATCH * H_; t += stride) {
        g_c0[t] = 0.f; g_c1[t] = 0.f; g_h0[t] = 0.f;
        long b = t / H_, j = t % H_;
        g_cat0_h[b * 768 + 256 + j] = z;  g_cat0_l[b * 768 + 256 + j] = z;
        g_cat1_h[b * 1024 + 512 + j] = z; g_cat1_l[b * 1024 + 512 + j] = z;
    }
}

// ---------------------------------------------------------------------------
// bf16x3 tensor-core NT GEMM:
//   C[m,n] = sum_k A[m,k]*B[n,k] (+bias[n]) (+Cin[m,n]) (relu?) -> fp32 C or bf16 hi/lo pair
// A,B given as bf16 hi/lo pairs (row-major, K contiguous). M%128==0, K%32==0. N guarded.
// ---------------------------------------------------------------------------
#define BM 128
#define BN 128
#define BK 32
#define SROW 20   // words per smem row (16 used + 4 pad) -> conflict-free LDS & 16B-aligned STS

#define MMA_BF16(cc, a0, a1, a2, a3, b0, b1)                                   \
    asm volatile("mma.sync.aligned.m16n8k16.row.col.f32.bf16.bf16.f32 "        \
                 "{%0,%1,%2,%3}, {%4,%5,%6,%7}, {%8,%9}, {%0,%1,%2,%3};\n"     \
                 : "+f"(cc[0]), "+f"(cc[1]), "+f"(cc[2]), "+f"(cc[3])          \
                 : "r"(a0), "r"(a1), "r"(a2), "r"(a3), "r"(b0), "r"(b1))

__global__ __launch_bounds__(256)
void gemm_bf16x3(const bf16* __restrict__ Ahi, const bf16* __restrict__ Alo, int lda, long sA,
                 const bf16* __restrict__ Bhi, const bf16* __restrict__ Blo, int ldb, long sB,
                 float* __restrict__ C, int ldc, long sC,
                 const float* __restrict__ Cin, long sCin,
                 const float* __restrict__ bias, long sBias,
                 bf16* __restrict__ OHi, bf16* __restrict__ OLo,
                 int M, int N, int K, int act)
{
    const int z = blockIdx.z;
    Ahi += z * sA; Alo += z * sA;
    Bhi += z * sB; Blo += z * sB;
    C   += z * sC;
    if (Cin)  Cin  += z * sCin;
    if (bias) bias += z * sBias;

    __shared__ uint32_t sAh[BM * SROW], sAl[BM * SROW];
    __shared__ uint32_t sBh[BN * SROW], sBl[BN * SROW];

    const int tid = threadIdx.x;
    const int m0 = blockIdx.y * BM;
    const int n0 = blockIdx.x * BN;
    const int lr = tid >> 2;      // 0..63  (row within tile)
    const int lq = tid & 3;       // 0..3   (uint4 column)

    const int wid = tid >> 5, lane = tid & 31;
    const int wm = (wid & 1) * 64;
    const int wn = (wid >> 1) * 32;
    const int gid = lane >> 2, qid = lane & 3;

    float c[4][4][4];
#pragma unroll
    for (int i = 0; i < 4; ++i)
#pragma unroll
        for (int j = 0; j < 4; ++j)
#pragma unroll
            for (int r = 0; r < 4; ++r) c[i][j][r] = 0.f;

    uint4 ra_h[2], ra_l[2], rb_h[2], rb_l[2];

    // prefetch first tile into registers
    {
#pragma unroll
        for (int r = 0; r < 2; ++r) {
            long offA = (long)(m0 + lr + r * 64) * lda + lq * 8;
            ra_h[r] = *(const uint4*)(Ahi + offA);
            ra_l[r] = *(const uint4*)(Alo + offA);
            int n = n0 + lr + r * 64;
            if (n < N) {
                long offB = (long)n * ldb + lq * 8;
                rb_h[r] = *(const uint4*)(Bhi + offB);
                rb_l[r] = *(const uint4*)(Blo + offB);
            } else {
                rb_h[r] = make_uint4(0, 0, 0, 0);
                rb_l[r] = make_uint4(0, 0, 0, 0);
            }
        }
    }

    for (int k0 = 0; k0 < K; k0 += BK) {
        // stage registers -> smem
#pragma unroll
        for (int r = 0; r < 2; ++r) {
            int row = lr + r * 64;
            *(uint4*)&sAh[row * SROW + lq * 4] = ra_h[r];
            *(uint4*)&sAl[row * SROW + lq * 4] = ra_l[r];
            *(uint4*)&sBh[row * SROW + lq * 4] = rb_h[r];
            *(uint4*)&sBl[row * SROW + lq * 4] = rb_l[r];
        }
        __syncthreads();

        // prefetch next tile
        if (k0 + BK < K) {
            int kn = k0 + BK;
#pragma unroll
            for (int r = 0; r < 2; ++r) {
                long offA = (long)(m0 + lr + r * 64) * lda + kn + lq * 8;
                ra_h[r] = *(const uint4*)(Ahi + offA);
                ra_l[r] = *(const uint4*)(Alo + offA);
                int n = n0 + lr + r * 64;
                if (n < N) {
                    long offB = (long)n * ldb + kn + lq * 8;
                    rb_h[r] = *(const uint4*)(Bhi + offB);
                    rb_l[r] = *(const uint4*)(Blo + offB);
                } else {
                    rb_h[r] = make_uint4(0, 0, 0, 0);
                    rb_l[r] = make_uint4(0, 0, 0, 0);
                }
            }
        }

        // compute 2 k16 steps
#pragma unroll
        for (int s = 0; s < 2; ++s) {
            const int kw = s * 8 + qid;
            uint32_t bh[4][2], bl[4][2];
#pragma unroll
            for (int j = 0; j < 4; ++j) {
                int rb = (wn + j * 8 + gid) * SROW + kw;
                bh[j][0] = sBh[rb];     bh[j][1] = sBh[rb + 4];
                bl[j][0] = sBl[rb];     bl[j][1] = sBl[rb + 4];
            }
#pragma unroll
            for (int i = 0; i < 4; ++i) {
                int ra = (wm + i * 16 + gid) * SROW + kw;
                uint32_t ah0 = sAh[ra],            ah1 = sAh[ra + 8 * SROW];
                uint32_t ah2 = sAh[ra + 4],        ah3 = sAh[ra + 8 * SROW + 4];
                uint32_t al0 = sAl[ra],            al1 = sAl[ra + 8 * SROW];
                uint32_t al2 = sAl[ra + 4],        al3 = sAl[ra + 8 * SROW + 4];
#pragma unroll
                for (int j = 0; j < 4; ++j) {
                    MMA_BF16(c[i][j], ah0, ah1, ah2, ah3, bh[j][0], bh[j][1]);
                    MMA_BF16(c[i][j], ah0, ah1, ah2, ah3, bl[j][0], bl[j][1]);
                    MMA_BF16(c[i][j], al0, al1, al2, al3, bh[j][0], bh[j][1]);
                }
            }
        }
        __syncthreads();
    }

    // epilogue
#pragma unroll
    for (int i = 0; i < 4; ++i) {
        const int mrow = m0 + wm + i * 16 + gid;
#pragma unroll
        for (int j = 0; j < 4; ++j) {
            const int nbase = n0 + wn + j * 8 + qid * 2;
#pragma unroll
            for (int hr = 0; hr < 2; ++hr) {
                const int m = mrow + hr * 8;
#pragma unroll
                for (int cc = 0; cc < 2; ++cc) {
                    const int n = nbase + cc;
                    if (n < N) {
                        float v = c[i][j][hr * 2 + cc];
                        if (bias) v += bias[n];
                        long idx = (long)m * ldc + n;
                        if (Cin) v += Cin[idx];
                        if (act == 1) v = fmaxf(v, 0.f);
                        if (OHi) bsplit(v, OHi + idx, OLo + idx);
                        else     C[idx] = v;
                    }
                }
            }
        }
    }
}

// ---------------------------------------------------------------------------
// Elementwise kernels
// ---------------------------------------------------------------------------
// write cur_emb into cat0 cols [0,E)
__global__ void build_cat0_emb(const float* __restrict__ start,
                               const float* __restrict__ emb,
                               const int* __restrict__ labels, int s)
{
    int idx = blockIdx.x * blockDim.x + threadIdx.x;
    if (idx >= BATCH * E_) return;
    int b = idx / E_, e = idx % E_;
    float v;
    if (s == 0) v = start[e];
    else {
        int lab = labels[(s - 1) * BATCH + b];
        v = emb[((long)(s - 1) * V_ + lab) * E_ + e];
    }
    long di = (long)b * 768 + e;
    bsplit(v, g_cat0_h + di, g_cat0_l + di);
}

// layer-0 LSTM pointwise; writes h0 fp32 + cat0 hi/lo cols [E, E+H)
__global__ void lstm_ew0()
{
    int idx = blockIdx.x * blockDim.x + threadIdx.x;
    if (idx >= BATCH * H_) return;
    int b = idx / H_, j = idx % H_;
    const float* g = g_gates + (long)b * H4_;
    float ig = sigm(g[j]);
    float fg = sigm(g[H_ + j]);
    float gg = tanhf(g[2 * H_ + j]);
    float og = sigm(g[3 * H_ + j]);
    float cn = fg * g_c0[idx] + ig * gg;
    float hn = og * tanhf(cn);
    g_c0[idx] = cn;
    g_h0[idx] = hn;
    long di = (long)b * 768 + E_ + j;
    bsplit(hn, g_cat0_h + di, g_cat0_l + di);
}

// highway combine -> cur; writes cat1 hi/lo cols [0,H)
__global__ void hwy_ew()
{
    int idx = blockIdx.x * blockDim.x + threadIdx.x;
    if (idx >= BATCH * H_) return;
    int b = idx / H_, j = idx % H_;
    float gg  = sigm(g_gateN[idx]);
    float cur = gg * g_h0[idx] + (1.f - gg) * g_lin[idx];
    long di = (long)b * 1024 + j;
    bsplit(cur, g_cat1_h + di, g_cat1_l + di);
}

// layer-1 LSTM pointwise; writes cat1 hi/lo cols [H, 2H)
__global__ void lstm_ew1()
{
    int idx = blockIdx.x * blockDim.x + threadIdx.x;
    if (idx >= BATCH * H_) return;
    int b = idx / H_, j = idx % H_;
    const float* g = g_gates + (long)b * H4_;
    float ig = sigm(g[j]);
    float fg = sigm(g[H_ + j]);
    float gg = tanhf(g[2 * H_ + j]);
    float og = sigm(g[3 * H_ + j]);
    float cn = fg * g_c1[idx] + ig * gg;
    float hn = og * tanhf(cn);
    g_c1[idx] = cn;
    long di = (long)b * 1024 + H_ + j;
    bsplit(hn, g_cat1_h + di, g_cat1_l + di);
}

// ---------------------------------------------------------------------------
// Host-side launch
// ---------------------------------------------------------------------------
#define SYM(var, sym) cudaGetSymbolAddress((void**)&var, sym)

static inline void G(const bf16* Ah, const bf16* Al, int lda, long sA,
                     const bf16* Bh, const bf16* Bl, int ldb, long sB,
                     float* C, int ldc, long sC,
                     const float* Cin, long sCin,
                     const float* bias, long sBias,
                     bf16* OHi, bf16* OLo,
                     int M, int N, int K, int act, int Z)
{
    dim3 grid((N + BN - 1) / BN, M / BM, Z);
    gemm_bf16x3<<<grid, 256>>>(Ah, Al, lda, sA, Bh, Bl, ldb, sB, C, ldc, sC,
                               Cin, sCin, bias, sBias, OHi, OLo, M, N, K, act);
}

extern "C" void kernel_launch(void* const* d_in, const int* in_sizes, int n_in,
                              void* d_out, int out_size)
{
    const float* inputs = (const float*)d_in[0];
    const int*   labels = (const int*)  d_in[1];
    const float* start  = (const float*)d_in[2];
    const float* emb    = (const float*)d_in[3];
    const float* W_ih0  = (const float*)d_in[4];
    const float* W_hh0  = (const float*)d_in[5];
    const float* b_ih0  = (const float*)d_in[6];
    const float* b_hh0  = (const float*)d_in[7];
    const float* hwN_W0 = (const float*)d_in[8];
    const float* hwN_b0 = (const float*)d_in[9];
    const float* hwL_W0 = (const float*)d_in[10];
    const float* W_ih1  = (const float*)d_in[11];
    const float* W_hh1  = (const float*)d_in[12];
    const float* b_ih1  = (const float*)d_in[13];
    const float* b_hh1  = (const float*)d_in[14];
    // d_in[15..17] dead in reference (layer-1 highway output unused)
    const float* sh_W   = (const float*)d_in[18];
    const float* sh_b   = (const float*)d_in[19];
    const float* pred_W = (const float*)d_in[20];
    const float* pred_b = (const float*)d_in[21];
    float* out = (float*)d_out;

    float *P_ih0, *P_N, *P_L, *bias0, *bias1, *gates, *gateN, *lin;
    bf16 *Wcat0_h, *Wcat0_l, *Wcat1_h, *Wcat1_l, *WihD_h, *WihD_l;
    bf16 *WND_h, *WND_l, *WLD_h, *WLD_l, *WNE_h, *WNE_l, *WLE_h, *WLE_l;
    bf16 *SHW_h, *SHW_l, *PW_h, *PW_l, *INP_h, *INP_l;
    bf16 *cat0_h, *cat0_l, *cat1_h, *cat1_l, *hid_h, *hid_l;
    SYM(P_ih0, g_P_ih0); SYM(P_N, g_P_N); SYM(P_L, g_P_L);
    SYM(bias0, g_bias0); SYM(bias1, g_bias1);
    SYM(gates, g_gates); SYM(gateN, g_gateN); SYM(lin, g_lin);
    SYM(Wcat0_h, g_Wcat0_h); SYM(Wcat0_l, g_Wcat0_l);
    SYM(Wcat1_h, g_Wcat1_h); SYM(Wcat1_l, g_Wcat1_l);
    SYM(WihD_h, g_WihD_h);   SYM(WihD_l, g_WihD_l);
    SYM(WND_h, g_WND_h); SYM(WND_l, g_WND_l);
    SYM(WLD_h, g_WLD_h); SYM(WLD_l, g_WLD_l);
    SYM(WNE_h, g_WNE_h); SYM(WNE_l, g_WNE_l);
    SYM(WLE_h, g_WLE_h); SYM(WLE_l, g_WLE_l);
    SYM(SHW_h, g_SHW_h); SYM(SHW_l, g_SHW_l);
    SYM(PW_h, g_PW_h);   SYM(PW_l, g_PW_l);
    SYM(INP_h, g_INP_h); SYM(INP_l, g_INP_l);
    SYM(cat0_h, g_cat0_h); SYM(cat0_l, g_cat0_l);
    SYM(cat1_h, g_cat1_h); SYM(cat1_l, g_cat1_l);
    SYM(hid_h, g_hid_h);   SYM(hid_l, g_hid_l);

    // ---- setup: weight/input splitting + init (independent kernels) ----
    const int CB = 4096;
    // Wcat0 = [W_ih0[:, D:] | W_hh0]
    conv_slice<<<CB, 256>>>(W_ih0, D0_, D_, Wcat0_h, Wcat0_l, 768, 0,   (long)S_ * H4_, E_);
    conv_slice<<<CB, 256>>>(W_hh0, H_,  0,  Wcat0_h, Wcat0_l, 768, E_,  (long)S_ * H4_, H_);
    // Wcat1 = [W_ih1 | W_hh1]
    conv_slice<<<CB, 256>>>(W_ih1, H_, 0, Wcat1_h, Wcat1_l, 1024, 0,  (long)S_ * H4_, H_);
    conv_slice<<<CB, 256>>>(W_hh1, H_, 0, Wcat1_h, Wcat1_l, 1024, H_, (long)S_ * H4_, H_);
    // inputs-facing weight slices
    conv_slice<<<CB, 256>>>(W_ih0,  D0_,       0, WihD_h, WihD_l, D_, 0, (long)S_ * H4_, D_);
    conv_slice<<<CB, 256>>>(hwN_W0, D0_ + H_,  0, WND_h,  WND_l,  D_, 0, (long)S_ * H_,  D_);
    conv_slice<<<CB, 256>>>(hwL_W0, D0_,       0, WLD_h,  WLD_l,  D_, 0, (long)S_ * H_,  D_);
    // recurrent-facing highway slices
    conv_slice<<<CB, 256>>>(hwN_W0, D0_ + H_, D_, WNE_h, WNE_l, 768, 0, (long)S_ * H_, E_ + H_);
    conv_slice<<<CB, 256>>>(hwL_W0, D0_,      D_, WLE_h, WLE_l, 256, 0, (long)S_ * H_, E_);
    // classifier weights
    conv_slice<<<CB, 256>>>(sh_W,   H_,  0, SHW_h, SHW_l, H_,  0, (long)S_ * SH_, H_);
    conv_slice<<<CB, 256>>>(pred_W, SH_, 0, PW_h,  PW_l,  SH_, 0, (long)S_ * V_,  SH_);
    // inputs
    conv_slice<<<CB, 256>>>(inputs, D_, 0, INP_h, INP_l, D_, 0, (long)BATCH, D_);
    // biases + zero states
    misc_init<<<CB, 256>>>(b_ih0, b_hh0, b_ih1, b_hh1);

    // ---- slot-parallel precompute (z = S) ----
    // P_ih0[s] = inputs @ W_ih0[s][:, :D].T + (b_ih0[s]+b_hh0[s])
    G(INP_h, INP_l, D_, 0, WihD_h, WihD_l, D_, (long)H4_ * D_,
      P_ih0, H4_, (long)BATCH * H4_, nullptr, 0, bias0, H4_,
      nullptr, nullptr, BATCH, H4_, D_, 0, S_);
    // P_N[s] = inputs @ hwN_W0[s][:, :D].T + hwN_b0[s]
    G(INP_h, INP_l, D_, 0, WND_h, WND_l, D_, (long)H_ * D_,
      P_N, H_, (long)BATCH * H_, nullptr, 0, hwN_b0, H_,
      nullptr, nullptr, BATCH, H_, D_, 0, S_);
    // P_L[s] = inputs @ hwL_W0[s][:, :D].T
    G(INP_h, INP_l, D_, 0, WLD_h, WLD_l, D_, (long)H_ * D_,
      P_L, H_, (long)BATCH * H_, nullptr, 0, nullptr, 0,
      nullptr, nullptr, BATCH, H_, D_, 0, S_);

    const int ewB  = (BATCH * H_ + 255) / 256;
    const int embB = (BATCH * E_ + 255) / 256;

    // ---- sequential slots ----
    for (int s = 0; s < S_; ++s) {
        build_cat0_emb<<<embB, 256>>>(start, emb, labels, s);

        // gates0 = cat0 @ Wcat0[s].T + P_ih0[s]
        G(cat0_h, cat0_l, 768, 0,
          Wcat0_h + (long)s * H4_ * 768, Wcat0_l + (long)s * H4_ * 768, 768, 0,
          gates, H4_, 0, P_ih0 + (long)s * BATCH * H4_, 0, nullptr, 0,
          nullptr, nullptr, BATCH, H4_, 768, 0, 1);

        lstm_ew0<<<ewB, 256>>>();

        // gateN = cat0 @ hwN_W0[s][:, D:].T + P_N[s]
        G(cat0_h, cat0_l, 768, 0,
          WNE_h + (long)s * H_ * 768, WNE_l + (long)s * H_ * 768, 768, 0,
          gateN, H_, 0, P_N + (long)s * BATCH * H_, 0, nullptr, 0,
          nullptr, nullptr, BATCH, H_, 768, 0, 1);

        // lin = cur_emb @ hwL_W0[s][:, D:].T + P_L[s]   (K = E)
        G(cat0_h, cat0_l, 768, 0,
          WLE_h + (long)s * H_ * 256, WLE_l + (long)s * H_ * 256, 256, 0,
          lin, H_, 0, P_L + (long)s * BATCH * H_, 0, nullptr, 0,
          nullptr, nullptr, BATCH, H_, 256, 0, 1);

        hwy_ew<<<ewB, 256>>>();

        // gates1 = cat1 @ Wcat1[s].T + bias1[s]
        G(cat1_h, cat1_l, 1024, 0,
          Wcat1_h + (long)s * H4_ * 1024, Wcat1_l + (long)s * H4_ * 1024, 1024, 0,
          gates, H4_, 0, nullptr, 0, bias1 + (long)s * H4_, 0,
          nullptr, nullptr, BATCH, H4_, 1024, 0, 1);

        lstm_ew1<<<ewB, 256>>>();

        // hidden = relu(h1 @ sh_W[s].T + sh_b[s])  -> bf16 hi/lo
        G(cat1_h + H_, cat1_l + H_, 1024, 0,
          SHW_h + (long)s * SH_ * H_, SHW_l + (long)s * SH_ * H_, H_, 0,
          nullptr, SH_, 0, nullptr, 0, sh_b + (long)s * SH_, 0,
          hid_h, hid_l, BATCH, SH_, H_, 1, 1);

        // logits[s] = hidden @ pred_W[s].T + pred_b[s]
        G(hid_h, hid_l, SH_, 0,
          PW_h + (long)s * V_ * SH_, PW_l + (long)s * V_ * SH_, SH_, 0,
          out + (long)s * BATCH * V_, V_, 0, nullptr, 0, pred_b + (long)s * V_, 0,
          nullptr, nullptr, BATCH, V_, SH_, 0, 1);
    }
}

// round 3
// speedup vs baseline: 1.8724x; 1.0015x over previous
#include <cuda_runtime.h>
#include <cuda_bf16.h>
#include <cstdint>

// ---------------------------------------------------------------------------
// Problem constants
// ---------------------------------------------------------------------------
#define S_   7
#define BATCH 8192
#define D_   1024
#define E_   256
#define H_   512
#define SH_  256
#define V_   100
#define D0_  (D_ + E_)     // 1280
#define H4_  (4 * H_)      // 2048

typedef __nv_bfloat16 bf16;

// ---------------------------------------------------------------------------
// Device scratch (static globals; no runtime allocation allowed)
// ---------------------------------------------------------------------------
// fp32 precomputed partials (Cin epilogue operands)
__device__ float g_P_ih0[S_ * BATCH * H4_];
__device__ float g_P_N  [S_ * BATCH * H_];
__device__ float g_P_L  [S_ * BATCH * H_];
// bf16 hi/lo weights (packed layouts, row-major, K contiguous)
__device__ bf16 g_Wcat0_h[S_ * H4_ * 768],  g_Wcat0_l[S_ * H4_ * 768];   // [Wih0_emb|Whh0]
__device__ bf16 g_Wcat1_h[S_ * H4_ * 1024], g_Wcat1_l[S_ * H4_ * 1024];  // [Wih1|Whh1]
__device__ bf16 g_WihD_h[S_ * H4_ * 1024],  g_WihD_l[S_ * H4_ * 1024];   // W_ih0[:, :D]
__device__ bf16 g_WND_h[S_ * H_ * 1024],    g_WND_l[S_ * H_ * 1024];     // hwN_W0[:, :D]
__device__ bf16 g_WLD_h[S_ * H_ * 1024],    g_WLD_l[S_ * H_ * 1024];     // hwL_W0[:, :D]
__device__ bf16 g_WNE_h[S_ * H_ * 768],     g_WNE_l[S_ * H_ * 768];      // hwN_W0[:, D:]
__device__ bf16 g_WLE_h[S_ * H_ * 256],     g_WLE_l[S_ * H_ * 256];      // hwL_W0[:, D:]
__device__ bf16 g_SHW_h[S_ * SH_ * H_],     g_SHW_l[S_ * SH_ * H_];
__device__ bf16 g_PW_h [S_ * V_ * SH_],     g_PW_l [S_ * V_ * SH_];
__device__ bf16 g_INP_h[BATCH * D_],        g_INP_l[BATCH * D_];
// bf16 hi/lo activations
__device__ bf16 g_cat0_h[BATCH * 768],  g_cat0_l[BATCH * 768];   // [emb | h0]
__device__ bf16 g_cat1_h[BATCH * 1024], g_cat1_l[BATCH * 1024];  // [cur | h1]
__device__ bf16 g_hid_h[BATCH * SH_],   g_hid_l[BATCH * SH_];
// fp32 state / temporaries
__device__ float g_gates[BATCH * H4_];
__device__ float g_gateN[BATCH * H_], g_lin[BATCH * H_];
__device__ float g_h0[BATCH * H_], g_c0[BATCH * H_], g_c1[BATCH * H_];
__device__ float g_bias0[S_ * H4_], g_bias1[S_ * H4_];

// ---------------------------------------------------------------------------
// Helpers
// ---------------------------------------------------------------------------
__device__ __forceinline__ void bsplit(float v, bf16* hp, bf16* lp) {
    bf16 h = __float2bfloat16(v);
    *hp = h;
    *lp = __float2bfloat16(v - __bfloat162float(h));
}
__device__ __forceinline__ float sigm(float x) { return 1.f / (1.f + expf(-x)); }

// ---------------------------------------------------------------------------
// Weight slice conversion: dst[r*dstStride + dstOff + c] = split(src[r*srcStride + srcOff + c])
// ---------------------------------------------------------------------------
__global__ void conv_slice(const float* __restrict__ src, long srcStride, long srcOff,
                           bf16* __restrict__ hi, bf16* __restrict__ lo,
                           long dstStride, long dstOff,
                           long rows, int cols)
{
    long total = rows * cols;
    long stride = (long)gridDim.x * blockDim.x;
    for (long t = blockIdx.x * (long)blockDim.x + threadIdx.x; t < total; t += stride) {
        long r = t / cols;
        int  c = (int)(t % cols);
        float v = src[r * srcStride + srcOff + c];
        long di = r * dstStride + dstOff + c;
        bsplit(v, hi + di, lo + di);
    }
}

// Misc init: fold biases, zero states and stale activation slices
__global__ void misc_init(const float* __restrict__ b_ih0, const float* __restrict__ b_hh0,
                          const float* __restrict__ b_ih1, const float* __restrict__ b_hh1)
{
    long stride = (long)gridDim.x * blockDim.x;
    for (long t = blockIdx.x * (long)blockDim.x + threadIdx.x; t < S_ * H4_; t += stride) {
        g_bias0[t] = b_ih0[t] + b_hh0[t];
        g_bias1[t] = b_ih1[t] + b_hh1[t];
    }
    bf16 z = __float2bfloat16(0.f);
    for (long t = blockIdx.x * (long)blockDim.x + threadIdx.x; t < (long)BATCH * H_; t += stride) {
        g_c0[t] = 0.f; g_c1[t] = 0.f; g_h0[t] = 0.f;
        long b = t / H_, j = t % H_;
        g_cat0_h[b * 768 + 256 + j] = z;  g_cat0_l[b * 768 + 256 + j] = z;
        g_cat1_h[b * 1024 + 512 + j] = z; g_cat1_l[b * 1024 + 512 + j] = z;
    }
}

// ---------------------------------------------------------------------------
// bf16x3 tensor-core NT GEMM:
//   C[m,n] = sum_k A[m,k]*B[n,k] (+bias[n]) (+Cin[m,n]) (relu?) -> fp32 C or bf16 hi/lo pair
// A,B given as bf16 hi/lo pairs (row-major, K contiguous). M%128==0, K%32==0. N guarded.
// ---------------------------------------------------------------------------
#define BM 128
#define BN 128
#define BK 32
#define SROW 20   // words per smem row (16 used + 4 pad) -> conflict-free LDS & 16B-aligned STS

#define MMA_BF16(cc, a0, a1, a2, a3, b0, b1)                                   \
    asm volatile("mma.sync.aligned.m16n8k16.row.col.f32.bf16.bf16.f32 "        \
                 "{%0,%1,%2,%3}, {%4,%5,%6,%7}, {%8,%9}, {%0,%1,%2,%3};\n"     \
                 : "+f"(cc[0]), "+f"(cc[1]), "+f"(cc[2]), "+f"(cc[3])          \
                 : "r"(a0), "r"(a1), "r"(a2), "r"(a3), "r"(b0), "r"(b1))

__global__ __launch_bounds__(256)
void gemm_bf16x3(const bf16* __restrict__ Ahi, const bf16* __restrict__ Alo, int lda, long sA,
                 const bf16* __restrict__ Bhi, const bf16* __restrict__ Blo, int ldb, long sB,
                 float* __restrict__ C, int ldc, long sC,
                 const float* __restrict__ Cin, long sCin,
                 const float* __restrict__ bias, long sBias,
                 bf16* __restrict__ OHi, bf16* __restrict__ OLo,
                 int M, int N, int K, int act)
{
    const int z = blockIdx.z;
    Ahi += z * sA; Alo += z * sA;
    Bhi += z * sB; Blo += z * sB;
    C   += z * sC;
    if (Cin)  Cin  += z * sCin;
    if (bias) bias += z * sBias;

    __shared__ uint32_t sAh[BM * SROW], sAl[BM * SROW];
    __shared__ uint32_t sBh[BN * SROW], sBl[BN * SROW];

    const int tid = threadIdx.x;
    const int m0 = blockIdx.y * BM;
    const int n0 = blockIdx.x * BN;
    const int lr = tid >> 2;      // 0..63  (row within tile)
    const int lq = tid & 3;       // 0..3   (uint4 column)

    const int wid = tid >> 5, lane = tid & 31;
    const int wm = (wid & 1) * 64;
    const int wn = (wid >> 1) * 32;
    const int gid = lane >> 2, qid = lane & 3;

    float c[4][4][4];
#pragma unroll
    for (int i = 0; i < 4; ++i)
#pragma unroll
        for (int j = 0; j < 4; ++j)
#pragma unroll
            for (int r = 0; r < 4; ++r) c[i][j][r] = 0.f;

    uint4 ra_h[2], ra_l[2], rb_h[2], rb_l[2];

    // prefetch first tile into registers
    {
#pragma unroll
        for (int r = 0; r < 2; ++r) {
            long offA = (long)(m0 + lr + r * 64) * lda + lq * 8;
            ra_h[r] = *(const uint4*)(Ahi + offA);
            ra_l[r] = *(const uint4*)(Alo + offA);
            int n = n0 + lr + r * 64;
            if (n < N) {
                long offB = (long)n * ldb + lq * 8;
                rb_h[r] = *(const uint4*)(Bhi + offB);
                rb_l[r] = *(const uint4*)(Blo + offB);
            } else {
                rb_h[r] = make_uint4(0, 0, 0, 0);
                rb_l[r] = make_uint4(0, 0, 0, 0);
            }
        }
    }

    for (int k0 = 0; k0 < K; k0 += BK) {
        // stage registers -> smem
#pragma unroll
        for (int r = 0; r < 2; ++r) {
            int row = lr + r * 64;
            *(uint4*)&sAh[row * SROW + lq * 4] = ra_h[r];
            *(uint4*)&sAl[row * SROW + lq * 4] = ra_l[r];
            *(uint4*)&sBh[row * SROW + lq * 4] = rb_h[r];
            *(uint4*)&sBl[row * SROW + lq * 4] = rb_l[r];
        }
        __syncthreads();

        // prefetch next tile
        if (k0 + BK < K) {
            int kn = k0 + BK;
#pragma unroll
            for (int r = 0; r < 2; ++r) {
                long offA = (long)(m0 + lr + r * 64) * lda + kn + lq * 8;
                ra_h[r] = *(const uint4*)(Ahi + offA);
                ra_l[r] = *(const uint4*)(Alo + offA);
                int n = n0 + lr + r * 64;
                if (n < N) {
                    long offB = (long)n * ldb + kn + lq * 8;
                    rb_h[r] = *(const uint4*)(Bhi + offB);
                    rb_l[r] = *(const uint4*)(Blo + offB);
                } else {
                    rb_h[r] = make_uint4(0, 0, 0, 0);
                    rb_l[r] = make_uint4(0, 0, 0, 0);
                }
            }
        }

        // compute 2 k16 steps
#pragma unroll
        for (int s = 0; s < 2; ++s) {
            const int kw = s * 8 + qid;
            uint32_t bh[4][2], bl[4][2];
#pragma unroll
            for (int j = 0; j < 4; ++j) {
                int rb = (wn + j * 8 + gid) * SROW + kw;
                bh[j][0] = sBh[rb];     bh[j][1] = sBh[rb + 4];
                bl[j][0] = sBl[rb];     bl[j][1] = sBl[rb + 4];
            }
#pragma unroll
            for (int i = 0; i < 4; ++i) {
                int ra = (wm + i * 16 + gid) * SROW + kw;
                uint32_t ah0 = sAh[ra],            ah1 = sAh[ra + 8 * SROW];
                uint32_t ah2 = sAh[ra + 4],        ah3 = sAh[ra + 8 * SROW + 4];
                uint32_t al0 = sAl[ra],            al1 = sAl[ra + 8 * SROW];
                uint32_t al2 = sAl[ra + 4],        al3 = sAl[ra + 8 * SROW + 4];
#pragma unroll
                for (int j = 0; j < 4; ++j) {
                    MMA_BF16(c[i][j], ah0, ah1, ah2, ah3, bh[j][0], bh[j][1]);
                    MMA_BF16(c[i][j], ah0, ah1, ah2, ah3, bl[j][0], bl[j][1]);
                    MMA_BF16(c[i][j], al0, al1, al2, al3, bh[j][0], bh[j][1]);
                }
            }
        }
        __syncthreads();
    }

    // epilogue
#pragma unroll
    for (int i = 0; i < 4; ++i) {
        const int mrow = m0 + wm + i * 16 + gid;
#pragma unroll
        for (int j = 0; j < 4; ++j) {
            const int nbase = n0 + wn + j * 8 + qid * 2;
#pragma unroll
            for (int hr = 0; hr < 2; ++hr) {
                const int m = mrow + hr * 8;
#pragma unroll
                for (int cc = 0; cc < 2; ++cc) {
                    const int n = nbase + cc;
                    if (n < N) {
                        float v = c[i][j][hr * 2 + cc];
                        if (bias) v += bias[n];
                        long idx = (long)m * ldc + n;
                        if (Cin) v += Cin[idx];
                        if (act == 1) v = fmaxf(v, 0.f);
                        if (OHi) bsplit(v, OHi + idx, OLo + idx);
                        else     C[idx] = v;
                    }
                }
            }
        }
    }
}

// ---------------------------------------------------------------------------
// Elementwise kernels
// ---------------------------------------------------------------------------
// write cur_emb into cat0 cols [0,E)
__global__ void build_cat0_emb(const float* __restrict__ start,
                               const float* __restrict__ emb,
                               const int* __restrict__ labels, int s)
{
    int idx = blockIdx.x * blockDim.x + threadIdx.x;
    if (idx >= BATCH * E_) return;
    int b = idx / E_, e = idx % E_;
    float v;
    if (s == 0) v = start[e];
    else {
        int lab = labels[(s - 1) * BATCH + b];
        v = emb[((long)(s - 1) * V_ + lab) * E_ + e];
    }
    long di = (long)b * 768 + e;
    bsplit(v, g_cat0_h + di, g_cat0_l + di);
}

// layer-0 LSTM pointwise; writes h0 fp32 + cat0 hi/lo cols [E, E+H)
__global__ void lstm_ew0()
{
    int idx = blockIdx.x * blockDim.x + threadIdx.x;
    if (idx >= BATCH * H_) return;
    int b = idx / H_, j = idx % H_;
    const float* g = g_gates + (long)b * H4_;
    float ig = sigm(g[j]);
    float fg = sigm(g[H_ + j]);
    float gg = tanhf(g[2 * H_ + j]);
    float og = sigm(g[3 * H_ + j]);
    float cn = fg * g_c0[idx] + ig * gg;
    float hn = og * tanhf(cn);
    g_c0[idx] = cn;
    g_h0[idx] = hn;
    long di = (long)b * 768 + E_ + j;
    bsplit(hn, g_cat0_h + di, g_cat0_l + di);
}

// highway combine -> cur; writes cat1 hi/lo cols [0,H)
__global__ void hwy_ew()
{
    int idx = blockIdx.x * blockDim.x + threadIdx.x;
    if (idx >= BATCH * H_) return;
    int b = idx / H_, j = idx % H_;
    float gg  = sigm(g_gateN[idx]);
    float cur = gg * g_h0[idx] + (1.f - gg) * g_lin[idx];
    long di = (long)b * 1024 + j;
    bsplit(cur, g_cat1_h + di, g_cat1_l + di);
}

// layer-1 LSTM pointwise; writes cat1 hi/lo cols [H, 2H)
__global__ void lstm_ew1()
{
    int idx = blockIdx.x * blockDim.x + threadIdx.x;
    if (idx >= BATCH * H_) return;
    int b = idx / H_, j = idx % H_;
    const float* g = g_gates + (long)b * H4_;
    float ig = sigm(g[j]);
    float fg = sigm(g[H_ + j]);
    float gg = tanhf(g[2 * H_ + j]);
    float og = sigm(g[3 * H_ + j]);
    float cn = fg * g_c1[idx] + ig * gg;
    float hn = og * tanhf(cn);
    g_c1[idx] = cn;
    long di = (long)b * 1024 + H_ + j;
    bsplit(hn, g_cat1_h + di, g_cat1_l + di);
}

// ---------------------------------------------------------------------------
// Host-side launch
// ---------------------------------------------------------------------------
#define SYM(var, sym) cudaGetSymbolAddress((void**)&var, sym)

static inline void G(const bf16* Ah, const bf16* Al, int lda, long sA,
                     const bf16* Bh, const bf16* Bl, int ldb, long sB,
                     float* C, int ldc, long sC,
                     const float* Cin, long sCin,
                     const float* bias, long sBias,
                     bf16* OHi, bf16* OLo,
                     int M, int N, int K, int act, int Z)
{
    dim3 grid((N + BN - 1) / BN, M / BM, Z);
    gemm_bf16x3<<<grid, 256>>>(Ah, Al, lda, sA, Bh, Bl, ldb, sB, C, ldc, sC,
                               Cin, sCin, bias, sBias, OHi, OLo, M, N, K, act);
}

extern "C" void kernel_launch(void* const* d_in, const int* in_sizes, int n_in,
                              void* d_out, int out_size)
{
    const float* inputs = (const float*)d_in[0];
    const int*   labels = (const int*)  d_in[1];
    const float* start  = (const float*)d_in[2];
    const float* emb    = (const float*)d_in[3];
    const float* W_ih0  = (const float*)d_in[4];
    const float* W_hh0  = (const float*)d_in[5];
    const float* b_ih0  = (const float*)d_in[6];
    const float* b_hh0  = (const float*)d_in[7];
    const float* hwN_W0 = (const float*)d_in[8];
    const float* hwN_b0 = (const float*)d_in[9];
    const float* hwL_W0 = (const float*)d_in[10];
    const float* W_ih1  = (const float*)d_in[11];
    const float* W_hh1  = (const float*)d_in[12];
    const float* b_ih1  = (const float*)d_in[13];
    const float* b_hh1  = (const float*)d_in[14];
    // d_in[15..17] dead in reference (layer-1 highway output unused)
    const float* sh_W   = (const float*)d_in[18];
    const float* sh_b   = (const float*)d_in[19];
    const float* pred_W = (const float*)d_in[20];
    const float* pred_b = (const float*)d_in[21];
    float* out = (float*)d_out;

    float *P_ih0, *P_N, *P_L, *bias0, *bias1, *gates, *gateN, *lin;
    bf16 *Wcat0_h, *Wcat0_l, *Wcat1_h, *Wcat1_l, *WihD_h, *WihD_l;
    bf16 *WND_h, *WND_l, *WLD_h, *WLD_l, *WNE_h, *WNE_l, *WLE_h, *WLE_l;
    bf16 *SHW_h, *SHW_l, *PW_h, *PW_l, *INP_h, *INP_l;
    bf16 *cat0_h, *cat0_l, *cat1_h, *cat1_l, *hid_h, *hid_l;
    SYM(P_ih0, g_P_ih0); SYM(P_N, g_P_N); SYM(P_L, g_P_L);
    SYM(bias0, g_bias0); SYM(bias1, g_bias1);
    SYM(gates, g_gates); SYM(gateN, g_gateN); SYM(lin, g_lin);
    SYM(Wcat0_h, g_Wcat0_h); SYM(Wcat0_l, g_Wcat0_l);
    SYM(Wcat1_h, g_Wcat1_h); SYM(Wcat1_l, g_Wcat1_l);
    SYM(WihD_h, g_WihD_h);   SYM(WihD_l, g_WihD_l);
    SYM(WND_h, g_WND_h); SYM(WND_l, g_WND_l);
    SYM(WLD_h, g_WLD_h); SYM(WLD_l, g_WLD_l);
    SYM(WNE_h, g_WNE_h); SYM(WNE_l, g_WNE_l);
    SYM(WLE_h, g_WLE_h); SYM(WLE_l, g_WLE_l);
    SYM(SHW_h, g_SHW_h); SYM(SHW_l, g_SHW_l);
    SYM(PW_h, g_PW_h);   SYM(PW_l, g_PW_l);
    SYM(INP_h, g_INP_h); SYM(INP_l, g_INP_l);
    SYM(cat0_h, g_cat0_h); SYM(cat0_l, g_cat0_l);
    SYM(cat1_h, g_cat1_h); SYM(cat1_l, g_cat1_l);
    SYM(hid_h, g_hid_h);   SYM(hid_l, g_hid_l);

    // ---- setup: weight/input splitting + init (independent kernels) ----
    const int CB = 4096;
    // Wcat0 = [W_ih0[:, D:] | W_hh0]
    conv_slice<<<CB, 256>>>(W_ih0, D0_, D_, Wcat0_h, Wcat0_l, 768, 0,   (long)S_ * H4_, E_);
    conv_slice<<<CB, 256>>>(W_hh0, H_,  0,  Wcat0_h, Wcat0_l, 768, E_,  (long)S_ * H4_, H_);
    // Wcat1 = [W_ih1 | W_hh1]
    conv_slice<<<CB, 256>>>(W_ih1, H_, 0, Wcat1_h, Wcat1_l, 1024, 0,  (long)S_ * H4_, H_);
    conv_slice<<<CB, 256>>>(W_hh1, H_, 0, Wcat1_h, Wcat1_l, 1024, H_, (long)S_ * H4_, H_);
    // inputs-facing weight slices
    conv_slice<<<CB, 256>>>(W_ih0,  D0_,       0, WihD_h, WihD_l, D_, 0, (long)S_ * H4_, D_);
    conv_slice<<<CB, 256>>>(hwN_W0, D0_ + H_,  0, WND_h,  WND_l,  D_, 0, (long)S_ * H_,  D_);
    conv_slice<<<CB, 256>>>(hwL_W0, D0_,       0, WLD_h,  WLD_l,  D_, 0, (long)S_ * H_,  D_);
    // recurrent-facing highway slices
    conv_slice<<<CB, 256>>>(hwN_W0, D0_ + H_, D_, WNE_h, WNE_l, 768, 0, (long)S_ * H_, E_ + H_);
    conv_slice<<<CB, 256>>>(hwL_W0, D0_,      D_, WLE_h, WLE_l, 256, 0, (long)S_ * H_, E_);
    // classifier weights
    conv_slice<<<CB, 256>>>(sh_W,   H_,  0, SHW_h, SHW_l, H_,  0, (long)S_ * SH_, H_);
    conv_slice<<<CB, 256>>>(pred_W, SH_, 0, PW_h,  PW_l,  SH_, 0, (long)S_ * V_,  SH_);
    // inputs
    conv_slice<<<CB, 256>>>(inputs, D_, 0, INP_h, INP_l, D_, 0, (long)BATCH, D_);
    // biases + zero states
    misc_init<<<CB, 256>>>(b_ih0, b_hh0, b_ih1, b_hh1);

    // ---- slot-parallel precompute (z = S) ----
    // P_ih0[s] = inputs @ W_ih0[s][:, :D].T + (b_ih0[s]+b_hh0[s])
    G(INP_h, INP_l, D_, 0, WihD_h, WihD_l, D_, (long)H4_ * D_,
      P_ih0, H4_, (long)BATCH * H4_, nullptr, 0, bias0, H4_,
      nullptr, nullptr, BATCH, H4_, D_, 0, S_);
    // P_N[s] = inputs @ hwN_W0[s][:, :D].T + hwN_b0[s]
    G(INP_h, INP_l, D_, 0, WND_h, WND_l, D_, (long)H_ * D_,
      P_N, H_, (long)BATCH * H_, nullptr, 0, hwN_b0, H_,
      nullptr, nullptr, BATCH, H_, D_, 0, S_);
    // P_L[s] = inputs @ hwL_W0[s][:, :D].T
    G(INP_h, INP_l, D_, 0, WLD_h, WLD_l, D_, (long)H_ * D_,
      P_L, H_, (long)BATCH * H_, nullptr, 0, nullptr, 0,
      nullptr, nullptr, BATCH, H_, D_, 0, S_);

    const int ewB  = (BATCH * H_ + 255) / 256;
    const int embB = (BATCH * E_ + 255) / 256;

    // ---- sequential slots ----
    for (int s = 0; s < S_; ++s) {
        build_cat0_emb<<<embB, 256>>>(start, emb, labels, s);

        // gates0 = cat0 @ Wcat0[s].T + P_ih0[s]
        G(cat0_h, cat0_l, 768, 0,
          Wcat0_h + (long)s * H4_ * 768, Wcat0_l + (long)s * H4_ * 768, 768, 0,
          gates, H4_, 0, P_ih0 + (long)s * BATCH * H4_, 0, nullptr, 0,
          nullptr, nullptr, BATCH, H4_, 768, 0, 1);

        lstm_ew0<<<ewB, 256>>>();

        // gateN = cat0 @ hwN_W0[s][:, D:].T + P_N[s]
        G(cat0_h, cat0_l, 768, 0,
          WNE_h + (long)s * H_ * 768, WNE_l + (long)s * H_ * 768, 768, 0,
          gateN, H_, 0, P_N + (long)s * BATCH * H_, 0, nullptr, 0,
          nullptr, nullptr, BATCH, H_, 768, 0, 1);

        // lin = cur_emb @ hwL_W0[s][:, D:].T + P_L[s]   (K = E)
        G(cat0_h, cat0_l, 768, 0,
          WLE_h + (long)s * H_ * 256, WLE_l + (long)s * H_ * 256, 256, 0,
          lin, H_, 0, P_L + (long)s * BATCH * H_, 0, nullptr, 0,
          nullptr, nullptr, BATCH, H_, 256, 0, 1);

        hwy_ew<<<ewB, 256>>>();

        // gates1 = cat1 @ Wcat1[s].T + bias1[s]
        G(cat1_h, cat1_l, 1024, 0,
          Wcat1_h + (long)s * H4_ * 1024, Wcat1_l + (long)s * H4_ * 1024, 1024, 0,
          gates, H4_, 0, nullptr, 0, bias1 + (long)s * H4_, 0,
          nullptr, nullptr, BATCH, H4_, 1024, 0, 1);

        lstm_ew1<<<ewB, 256>>>();

        // hidden = relu(h1 @ sh_W[s].T + sh_b[s])  -> bf16 hi/lo
        G(cat1_h + H_, cat1_l + H_, 1024, 0,
          SHW_h + (long)s * SH_ * H_, SHW_l + (long)s * SH_ * H_, H_, 0,
          nullptr, SH_, 0, nullptr, 0, sh_b + (long)s * SH_, 0,
          hid_h, hid_l, BATCH, SH_, H_, 1, 1);

        // logits[s] = hidden @ pred_W[s].T + pred_b[s]
        G(hid_h, hid_l, SH_, 0,
          PW_h + (long)s * V_ * SH_, PW_l + (long)s * V_ * SH_, SH_, 0,
          out + (long)s * BATCH * V_, V_, 0, nullptr, 0, pred_b + (long)s * V_, 0,
          nullptr, nullptr, BATCH, V_, SH_, 0, 1);
    }
}

// round 5
// speedup vs baseline: 2.5546x; 1.3643x over previous
#include <cuda_runtime.h>
#include <cuda_bf16.h>
#include <cstdint>

// ---------------------------------------------------------------------------
// Problem constants
// ---------------------------------------------------------------------------
#define S_   7
#define BATCH 8192
#define D_   1024
#define E_   256
#define H_   512
#define SH_  256
#define V_   100
#define D0_  (D_ + E_)     // 1280
#define H4_  (4 * H_)      // 2048

typedef __nv_bfloat16 bf16;

// Packed K sizes (K' = 3K)
#define KP_CAT0  2304   // 3*768
#define KP_CAT1  3072   // 3*1024
#define KP_D     3072   // 3*1024
#define KP_H1    1536   // 3*512
#define KP_HID   768    // 3*256

// ---------------------------------------------------------------------------
// Device scratch
// ---------------------------------------------------------------------------
__device__ float g_P_ih0[S_ * BATCH * H4_];          // 469 MB
__device__ float g_P_NL [S_ * BATCH * 1024];         // 235 MB
// packed bf16 weights  (B-side layout [Bh | Bh | Bl])
__device__ bf16 g_Wcat0[S_ * H4_ * KP_CAT0];         // [Wih0_emb | Whh0]
__device__ bf16 g_Wcat1[S_ * H4_ * KP_CAT1];         // [Wih1 | Whh1]
__device__ bf16 g_WihD [S_ * H4_ * KP_D];            // W_ih0[:, :D]
__device__ bf16 g_WNLD [S_ * 1024 * KP_D];           // rows 0-511 hwN[:, :D], 512-1023 hwL[:, :D]
__device__ bf16 g_WNL  [S_ * 1024 * KP_CAT0];        // rows 0-511 hwN[:, D:], 512-1023 hwL[:, D:] zero-padded
__device__ bf16 g_SHW  [S_ * SH_ * KP_H1];
__device__ bf16 g_PW   [S_ * V_  * KP_HID];
// packed bf16 activations (A-side layout [Ah | Al | Ah])
__device__ bf16 g_INP  [BATCH * KP_D];
__device__ bf16 g_cat0 [BATCH * KP_CAT0];            // orig [emb(256) | h0(512)]
__device__ bf16 g_cat1 [BATCH * KP_CAT1];            // orig [cur(512) | h1(512)]
__device__ bf16 g_h1p  [BATCH * KP_H1];
__device__ bf16 g_hid  [BATCH * KP_HID];
// fp32 temporaries / state
__device__ float g_gates[BATCH * H4_];
__device__ float g_gNL  [BATCH * 1024];
__device__ float g_h0[BATCH * H_], g_c0[BATCH * H_], g_c1[BATCH * H_];
__device__ float g_bias0[S_ * H4_], g_bias1[S_ * H4_], g_biasNL[S_ * 1024];

// ---------------------------------------------------------------------------
// PTX helpers
// ---------------------------------------------------------------------------
__device__ __forceinline__ uint32_t smem_u32(const void* p) {
    uint32_t a;
    asm("{ .reg .u64 t; cvta.to.shared.u64 t, %1; cvt.u32.u64 %0, t; }" : "=r"(a) : "l"(p));
    return a;
}
__device__ __forceinline__ uint32_t sw128(uint32_t off) { return off ^ ((off >> 3) & 0x70); }

__device__ __forceinline__ void cpa16(uint32_t dst, const void* src, int sz) {
    asm volatile("cp.async.cg.shared.global [%0], [%1], 16, %2;"
                 :: "r"(dst), "l"(src), "r"(sz) : "memory");
}
__device__ __forceinline__ void ldsm4(uint32_t* r, uint32_t addr) {
    asm volatile("ldmatrix.sync.aligned.m8n8.x4.shared.b16 {%0,%1,%2,%3}, [%4];"
                 : "=r"(r[0]), "=r"(r[1]), "=r"(r[2]), "=r"(r[3]) : "r"(addr));
}
#define MMA_BF16(cc, a0, a1, a2, a3, b0, b1)                                   \
    asm volatile("mma.sync.aligned.m16n8k16.row.col.f32.bf16.bf16.f32 "        \
                 "{%0,%1,%2,%3}, {%4,%5,%6,%7}, {%8,%9}, {%0,%1,%2,%3};\n"     \
                 : "+f"(cc[0]), "+f"(cc[1]), "+f"(cc[2]), "+f"(cc[3])          \
                 : "r"(a0), "r"(a1), "r"(a2), "r"(a3), "r"(b0), "r"(b1))

__device__ __forceinline__ float sigm(float x) { return 1.f / (1.f + expf(-x)); }

// ---------------------------------------------------------------------------
// Weight / input packing.
// dst row = (r / rps) * drps + dro + (r % rps); dst cols: hi @ colOff+c,
// lo @ loOff+colOff+c, hi2 @ h2Off+colOff+c.
//   B-side: loOff = 2*Kp, h2Off = Kp   ([Bh|Bh|Bl])
//   A-side: loOff = Kp,   h2Off = 2*Kp ([Ah|Al|Ah])
// ---------------------------------------------------------------------------
__global__ void conv_pack(const float* __restrict__ src, long srcStride, long srcOff,
                          bf16* __restrict__ dst, long dstLd, int colOff,
                          int loOff, int h2Off,
                          long rows, int cols, int rps, int drps, int dro)
{
    int c4n = cols >> 2;
    long total = rows * c4n;
    long stride = (long)gridDim.x * blockDim.x;
    for (long t = blockIdx.x * (long)blockDim.x + threadIdx.x; t < total; t += stride) {
        long r = t / c4n;
        int  c = (int)(t - r * c4n) << 2;
        float4 v = *reinterpret_cast<const float4*>(src + r * srcStride + srcOff + c);
        bf16 h0 = __float2bfloat16(v.x), h1 = __float2bfloat16(v.y);
        bf16 h2 = __float2bfloat16(v.z), h3 = __float2bfloat16(v.w);
        bf16 l0 = __float2bfloat16(v.x - __bfloat162float(h0));
        bf16 l1 = __float2bfloat16(v.y - __bfloat162float(h1));
        bf16 l2 = __float2bfloat16(v.z - __bfloat162float(h2));
        bf16 l3 = __float2bfloat16(v.w - __bfloat162float(h3));
        long dr = (r / rps) * (long)drps + dro + (r % rps);
        long base = dr * dstLd + colOff + c;
        __nv_bfloat162* p;
        p = (__nv_bfloat162*)(dst + base);
        p[0] = __nv_bfloat162(h0, h1); p[1] = __nv_bfloat162(h2, h3);
        p = (__nv_bfloat162*)(dst + base + loOff);
        p[0] = __nv_bfloat162(l0, l1); p[1] = __nv_bfloat162(l2, l3);
        p = (__nv_bfloat162*)(dst + base + h2Off);
        p[0] = __nv_bfloat162(h0, h1); p[1] = __nv_bfloat162(h2, h3);
    }
}

__global__ void zero_bf16(bf16* __restrict__ p, long nWords)  // nWords = elems/2
{
    long stride = (long)gridDim.x * blockDim.x;
    uint32_t* w = (uint32_t*)p;
    for (long t = blockIdx.x * (long)blockDim.x + threadIdx.x; t < nWords; t += stride)
        w[t] = 0u;
}

__global__ void misc_init(const float* __restrict__ b_ih0, const float* __restrict__ b_hh0,
                          const float* __restrict__ b_ih1, const float* __restrict__ b_hh1,
                          const float* __restrict__ hwN_b0)
{
    long stride = (long)gridDim.x * blockDim.x;
    long idx0 = blockIdx.x * (long)blockDim.x + threadIdx.x;
    for (long t = idx0; t < S_ * H4_; t += stride) {
        g_bias0[t] = b_ih0[t] + b_hh0[t];
        g_bias1[t] = b_ih1[t] + b_hh1[t];
    }
    for (long t = idx0; t < S_ * 1024; t += stride) {
        long s = t / 1024, j = t % 1024;
        g_biasNL[t] = (j < 512) ? hwN_b0[s * 512 + j] : 0.f;
    }
    bf16 z = __float2bfloat16(0.f);
    for (long t = idx0; t < (long)BATCH * H_; t += stride) {
        g_c0[t] = 0.f; g_c1[t] = 0.f; g_h0[t] = 0.f;
        long b = t / H_, j = t % H_;
        bf16* c0p = g_cat0 + b * KP_CAT0;
        c0p[256 + j] = z; c0p[1024 + j] = z; c0p[1792 + j] = z;
        bf16* c1p = g_cat1 + b * KP_CAT1;
        c1p[512 + j] = z; c1p[1536 + j] = z; c1p[2560 + j] = z;
    }
}

// ---------------------------------------------------------------------------
// Pipelined bf16 NT GEMM (K-packed split), mma.sync + cp.async + ldmatrix.
//   C[m,n] = sum_k A[m,k]*B[n,k] (+bias) (+Cin) (relu) -> fp32 C or packed bf16 OP
//   M%128==0, K%64==0, N even (tail guarded).
// ---------------------------------------------------------------------------
#define BM 128
#define BN 128
#define BK 64
#define STG_BYTES 16384           // 128 rows x 128B
#define SMEM_GEMM (6 * STG_BYTES) // 3 stages x (A+B) = 98304

__global__ __launch_bounds__(256, 2)
void gemm_mma(const bf16* __restrict__ A, int lda, long sA,
              const bf16* __restrict__ B, int ldb, long sB,
              float* __restrict__ C, int ldc, long sC,
              const float* __restrict__ Cin, long sCin,
              const float* __restrict__ bias, long sBias,
              bf16* __restrict__ OP, int ldo, int P,
              int M, int N, int K, int act)
{
    extern __shared__ char smem[];
    const uint32_t sbA = smem_u32(smem);
    const uint32_t sbB = sbA + 3 * STG_BYTES;

    const int z = blockIdx.z;
    A += z * sA;  B += z * sB;  C += z * sC;
    if (Cin)  Cin  += z * sCin;
    if (bias) bias += z * sBias;

    const int tid = threadIdx.x;
    const int warp = tid >> 5, lane = tid & 31;
    const int m0 = blockIdx.y * BM, n0 = blockIdx.x * BN;
    const int wm = (warp & 1) * 64, wn = (warp >> 1) * 32;

    float c[4][4][4];
#pragma unroll
    for (int i = 0; i < 4; ++i)
#pragma unroll
        for (int j = 0; j < 4; ++j)
#pragma unroll
            for (int r = 0; r < 4; ++r) c[i][j][r] = 0.f;

    const int kT = K / BK;

    auto issue = [&](int t) {
        const int kk = t * BK;
        const uint32_t aBuf = sbA + (t % 3) * STG_BYTES;
        const uint32_t bBuf = sbB + (t % 3) * STG_BYTES;
#pragma unroll
        for (int w = 0; w < 4; ++w) {
            int g = tid + w * 256;
            int row = g >> 3, q = g & 7;
            const char* srcA = (const char*)(A + (long)(m0 + row) * lda + kk) + q * 16;
            cpa16(aBuf + sw128(row * 128 + q * 16), srcA, 16);
        }
#pragma unroll
        for (int w = 0; w < 4; ++w) {
            int g = tid + w * 256;
            int row = g >> 3, q = g & 7;
            int n = n0 + row;
            const char* srcB = (const char*)(B + (long)n * ldb + kk) + q * 16;
            cpa16(bBuf + sw128(row * 128 + q * 16), (n < N) ? srcB : (const char*)B,
                  (n < N) ? 16 : 0);
        }
        asm volatile("cp.async.commit_group;" ::: "memory");
    };

    issue(0);
    if (kT > 1) issue(1);

    for (int t = 0; t < kT; ++t) {
        if (t + 1 < kT) asm volatile("cp.async.wait_group 1;" ::: "memory");
        else            asm volatile("cp.async.wait_group 0;" ::: "memory");
        __syncthreads();
        if (t + 2 < kT) issue(t + 2);

        const uint32_t aS = sbA + (t % 3) * STG_BYTES;
        const uint32_t bS = sbB + (t % 3) * STG_BYTES;
#pragma unroll
        for (int ks = 0; ks < 4; ++ks) {
            uint32_t a[4][4], b[2][4];
            const int colByte = (ks * 16 + ((lane >> 4) << 3)) * 2;
#pragma unroll
            for (int i = 0; i < 4; ++i)
                ldsm4(a[i], aS + sw128((wm + i * 16 + (lane & 15)) * 128 + colByte));
#pragma unroll
            for (int jb = 0; jb < 2; ++jb)
                ldsm4(b[jb], bS + sw128((wn + jb * 16 + (lane & 15)) * 128 + colByte));
#pragma unroll
            for (int i = 0; i < 4; ++i)
#pragma unroll
                for (int j = 0; j < 4; ++j) {
                    const int jb = j >> 1, sel = j & 1;
                    MMA_BF16(c[i][j], a[i][0], a[i][1], a[i][2], a[i][3],
                             b[jb][sel], b[jb][sel + 2]);
                }
        }
    }

    // epilogue: thread (lane) holds c[i][j][r]: m = m0+wm+i*16+(lane>>2)+8*(r>>1),
    // n = n0+wn+j*8+(lane&3)*2+(r&1)
#pragma unroll
    for (int i = 0; i < 4; ++i) {
#pragma unroll
        for (int rr = 0; rr < 2; ++rr) {
            const int m = m0 + wm + i * 16 + (lane >> 2) + rr * 8;
#pragma unroll
            for (int j = 0; j < 4; ++j) {
                const int n = n0 + wn + j * 8 + (lane & 3) * 2;
                if (n < N) {   // N even -> pair fully valid
                    float v0 = c[i][j][rr * 2 + 0];
                    float v1 = c[i][j][rr * 2 + 1];
                    if (bias) { v0 += bias[n]; v1 += bias[n + 1]; }
                    const long idx = (long)m * ldc + n;
                    if (Cin) { v0 += Cin[idx]; v1 += Cin[idx + 1]; }
                    if (act) { v0 = fmaxf(v0, 0.f); v1 = fmaxf(v1, 0.f); }
                    if (OP) {
                        const long o = (long)m * ldo + n;
                        bf16 h0 = __float2bfloat16(v0), h1 = __float2bfloat16(v1);
                        bf16 l0 = __float2bfloat16(v0 - __bfloat162float(h0));
                        bf16 l1 = __float2bfloat16(v1 - __bfloat162float(h1));
                        *(__nv_bfloat162*)(OP + o)         = __nv_bfloat162(h0, h1);
                        *(__nv_bfloat162*)(OP + o + P)     = __nv_bfloat162(l0, l1);
                        *(__nv_bfloat162*)(OP + o + 2 * P) = __nv_bfloat162(h0, h1);
                    } else {
                        float2 st; st.x = v0; st.y = v1;
                        *(float2*)(C + idx) = st;
                    }
                }
            }
        }
    }
}

// ---------------------------------------------------------------------------
// Elementwise kernels (packed-layout writers)
// ---------------------------------------------------------------------------
__device__ __forceinline__ void packA3(bf16* base, long o, int Kp, float v) {
    bf16 h = __float2bfloat16(v);
    bf16 l = __float2bfloat16(v - __bfloat162float(h));
    base[o] = h; base[o + Kp] = l; base[o + 2 * Kp] = h;
}

__global__ void build_cat0_emb(const float* __restrict__ start,
                               const float* __restrict__ emb,
                               const int* __restrict__ labels, int s)
{
    int idx = blockIdx.x * blockDim.x + threadIdx.x;
    if (idx >= BATCH * E_) return;
    int b = idx / E_, e = idx % E_;
    float v;
    if (s == 0) v = start[e];
    else {
        int lab = labels[(s - 1) * BATCH + b];
        v = emb[((long)(s - 1) * V_ + lab) * E_ + e];
    }
    packA3(g_cat0, (long)b * KP_CAT0 + e, 768, v);
}

__global__ void lstm_ew0()
{
    int idx = blockIdx.x * blockDim.x + threadIdx.x;
    if (idx >= BATCH * H_) return;
    int b = idx / H_, j = idx % H_;
    const float* g = g_gates + (long)b * H4_;
    float ig = sigm(g[j]);
    float fg = sigm(g[H_ + j]);
    float gg = tanhf(g[2 * H_ + j]);
    float og = sigm(g[3 * H_ + j]);
    float cn = fg * g_c0[idx] + ig * gg;
    float hn = og * tanhf(cn);
    g_c0[idx] = cn;
    g_h0[idx] = hn;
    packA3(g_cat0, (long)b * KP_CAT0 + 256 + j, 768, hn);
}

__global__ void hwy_ew()
{
    int idx = blockIdx.x * blockDim.x + threadIdx.x;
    if (idx >= BATCH * H_) return;
    int b = idx / H_, j = idx % H_;
    float gg  = sigm(g_gNL[(long)b * 1024 + j]);
    float cur = gg * g_h0[idx] + (1.f - gg) * g_gNL[(long)b * 1024 + 512 + j];
    packA3(g_cat1, (long)b * KP_CAT1 + j, 1024, cur);
}

__global__ void lstm_ew1()
{
    int idx = blockIdx.x * blockDim.x + threadIdx.x;
    if (idx >= BATCH * H_) return;
    int b = idx / H_, j = idx % H_;
    const float* g = g_gates + (long)b * H4_;
    float ig = sigm(g[j]);
    float fg = sigm(g[H_ + j]);
    float gg = tanhf(g[2 * H_ + j]);
    float og = sigm(g[3 * H_ + j]);
    float cn = fg * g_c1[idx] + ig * gg;
    float hn = og * tanhf(cn);
    g_c1[idx] = cn;
    packA3(g_cat1, (long)b * KP_CAT1 + 512 + j, 1024, hn);   // for next slot's gates1
    packA3(g_h1p,  (long)b * KP_H1 + j,          512, hn);   // for this slot's sh GEMM
}

// ---------------------------------------------------------------------------
// Host-side launch
// ---------------------------------------------------------------------------
#define SYM(var, sym) cudaGetSymbolAddress((void**)&var, sym)

static inline void G(const bf16* A, int lda, long sA,
                     const bf16* B, int ldb, long sB,
                     float* C, int ldc, long sC,
                     const float* Cin, long sCin,
                     const float* bias, long sBias,
                     bf16* OP, int ldo, int P,
                     int M, int N, int K, int act, int Z)
{
    dim3 grid((N + BN - 1) / BN, M / BM, Z);
    gemm_mma<<<grid, 256, SMEM_GEMM>>>(A, lda, sA, B, ldb, sB, C, ldc, sC,
                                       Cin, sCin, bias, sBias, OP, ldo, P,
                                       M, N, K, act);
}

extern "C" void kernel_launch(void* const* d_in, const int* in_sizes, int n_in,
                              void* d_out, int out_size)
{
    const float* inputs = (const float*)d_in[0];
    const int*   labels = (const int*)  d_in[1];
    const float* start  = (const float*)d_in[2];
    const float* emb    = (const float*)d_in[3];
    const float* W_ih0  = (const float*)d_in[4];
    const float* W_hh0  = (const float*)d_in[5];
    const float* b_ih0  = (const float*)d_in[6];
    const float* b_hh0  = (const float*)d_in[7];
    const float* hwN_W0 = (const float*)d_in[8];
    const float* hwN_b0 = (const float*)d_in[9];
    const float* hwL_W0 = (const float*)d_in[10];
    const float* W_ih1  = (const float*)d_in[11];
    const float* W_hh1  = (const float*)d_in[12];
    const float* b_ih1  = (const float*)d_in[13];
    const float* b_hh1  = (const float*)d_in[14];
    // d_in[15..17] dead in reference (layer-1 highway output unused)
    const float* sh_W   = (const float*)d_in[18];
    const float* sh_b   = (const float*)d_in[19];
    const float* pred_W = (const float*)d_in[20];
    const float* pred_b = (const float*)d_in[21];
    float* out = (float*)d_out;

    static bool attrSet = false;
    if (!attrSet) {
        cudaFuncSetAttribute(gemm_mma, cudaFuncAttributeMaxDynamicSharedMemorySize,
                             SMEM_GEMM);
        attrSet = true;
    }

    float *P_ih0, *P_NL, *bias0, *bias1, *biasNL, *gates, *gNL;
    bf16 *Wcat0, *Wcat1, *WihD, *WNLD, *WNL, *SHW, *PW, *INP;
    bf16 *cat0, *cat1, *h1p, *hid;
    SYM(P_ih0, g_P_ih0); SYM(P_NL, g_P_NL);
    SYM(bias0, g_bias0); SYM(bias1, g_bias1); SYM(biasNL, g_biasNL);
    SYM(gates, g_gates); SYM(gNL, g_gNL);
    SYM(Wcat0, g_Wcat0); SYM(Wcat1, g_Wcat1); SYM(WihD, g_WihD);
    SYM(WNLD, g_WNLD);   SYM(WNL, g_WNL);
    SYM(SHW, g_SHW);     SYM(PW, g_PW);       SYM(INP, g_INP);
    SYM(cat0, g_cat0);   SYM(cat1, g_cat1);
    SYM(h1p, g_h1p);     SYM(hid, g_hid);

    // ---- setup: packing (B-side: lo=2Kp, h2=Kp; A-side: lo=Kp, h2=2Kp) ----
    const int CB = 2048;
    const int BIG = 1 << 30;
    // Wcat0 (Kp=768): [W_ih0 emb cols | W_hh0]
    conv_pack<<<CB, 256>>>(W_ih0, D0_, D_, Wcat0, KP_CAT0, 0,   1536, 768,
                           (long)S_ * H4_, 256, BIG, 0, 0);
    conv_pack<<<CB, 256>>>(W_hh0, H_, 0,   Wcat0, KP_CAT0, 256, 1536, 768,
                           (long)S_ * H4_, 512, BIG, 0, 0);
    // Wcat1 (Kp=1024): [W_ih1 | W_hh1]
    conv_pack<<<CB, 256>>>(W_ih1, H_, 0, Wcat1, KP_CAT1, 0,   2048, 1024,
                           (long)S_ * H4_, 512, BIG, 0, 0);
    conv_pack<<<CB, 256>>>(W_hh1, H_, 0, Wcat1, KP_CAT1, 512, 2048, 1024,
                           (long)S_ * H4_, 512, BIG, 0, 0);
    // WihD (Kp=1024): W_ih0[:, :D]
    conv_pack<<<CB, 256>>>(W_ih0, D0_, 0, WihD, KP_D, 0, 2048, 1024,
                           (long)S_ * H4_, 1024, BIG, 0, 0);
    // WNLD (Kp=1024): stacked hwN[:, :D] / hwL[:, :D] per slot
    conv_pack<<<CB, 256>>>(hwN_W0, D0_ + H_, 0, WNLD, KP_D, 0, 2048, 1024,
                           (long)S_ * H_, 1024, 512, 1024, 0);
    conv_pack<<<CB, 256>>>(hwL_W0, D0_, 0,      WNLD, KP_D, 0, 2048, 1024,
                           (long)S_ * H_, 1024, 512, 1024, 512);
    // WNL (Kp=768): stacked hwN[:, D:] (768 cols) / hwL[:, D:] (256 cols, zero-padded)
    zero_bf16<<<CB, 256>>>(WNL, (long)S_ * 1024 * KP_CAT0 / 2);
    conv_pack<<<CB, 256>>>(hwN_W0, D0_ + H_, D_, WNL, KP_CAT0, 0, 1536, 768,
                           (long)S_ * H_, 768, 512, 1024, 0);
    conv_pack<<<CB, 256>>>(hwL_W0, D0_, D_,      WNL, KP_CAT0, 0, 1536, 768,
                           (long)S_ * H_, 256, 512, 1024, 512);
    // SHW (Kp=512), PW (Kp=256)
    conv_pack<<<CB, 256>>>(sh_W, H_, 0,    SHW, KP_H1, 0, 1024, 512,
                           (long)S_ * SH_, 512, BIG, 0, 0);
    conv_pack<<<CB, 256>>>(pred_W, SH_, 0, PW, KP_HID, 0, 512, 256,
                           (long)S_ * V_, 256, BIG, 0, 0);
    // INP: A-side (lo=Kp, h2=2Kp)
    conv_pack<<<CB, 256>>>(inputs, D_, 0, INP, KP_D, 0, 1024, 2048,
                           (long)BATCH, 1024, BIG, 0, 0);
    misc_init<<<CB, 256>>>(b_ih0, b_hh0, b_ih1, b_hh1, hwN_b0);

    // ---- slot-parallel precompute (grid.z = S) ----
    G(INP, KP_D, 0, WihD, KP_D, (long)H4_ * KP_D,
      P_ih0, H4_, (long)BATCH * H4_, nullptr, 0, bias0, H4_,
      nullptr, 0, 0, BATCH, H4_, KP_D, 0, S_);
    G(INP, KP_D, 0, WNLD, KP_D, (long)1024 * KP_D,
      P_NL, 1024, (long)BATCH * 1024, nullptr, 0, biasNL, 1024,
      nullptr, 0, 0, BATCH, 1024, KP_D, 0, S_);

    const int ewB  = (BATCH * H_ + 255) / 256;
    const int embB = (BATCH * E_ + 255) / 256;

    // ---- sequential slots ----
    for (int s = 0; s < S_; ++s) {
        build_cat0_emb<<<embB, 256>>>(start, emb, labels, s);

        // gates0 = cat0 @ Wcat0[s].T + P_ih0[s]
        G(cat0, KP_CAT0, 0, Wcat0 + (long)s * H4_ * KP_CAT0, KP_CAT0, 0,
          gates, H4_, 0, P_ih0 + (long)s * BATCH * H4_, 0, nullptr, 0,
          nullptr, 0, 0, BATCH, H4_, KP_CAT0, 0, 1);

        lstm_ew0<<<ewB, 256>>>();

        // [gateN | lin] = cat0 @ WNL[s].T + P_NL[s]
        G(cat0, KP_CAT0, 0, WNL + (long)s * 1024 * KP_CAT0, KP_CAT0, 0,
          gNL, 1024, 0, P_NL + (long)s * BATCH * 1024, 0, nullptr, 0,
          nullptr, 0, 0, BATCH, 1024, KP_CAT0, 0, 1);

        hwy_ew<<<ewB, 256>>>();

        // gates1 = cat1 @ Wcat1[s].T + bias1[s]
        G(cat1, KP_CAT1, 0, Wcat1 + (long)s * H4_ * KP_CAT1, KP_CAT1, 0,
          gates, H4_, 0, nullptr, 0, bias1 + (long)s * H4_, 0,
          nullptr, 0, 0, BATCH, H4_, KP_CAT1, 0, 1);

        lstm_ew1<<<ewB, 256>>>();

        // hidden = relu(h1 @ sh_W[s].T + sh_b[s]) -> packed bf16
        G(h1p, KP_H1, 0, SHW + (long)s * SH_ * KP_H1, KP_H1, 0,
          nullptr, SH_, 0, nullptr, 0, sh_b + (long)s * SH_, 0,
          hid, KP_HID, 256, BATCH, SH_, KP_H1, 1, 1);

        // logits[s] = hidden @ pred_W[s].T + pred_b[s]
        G(hid, KP_HID, 0, PW + (long)s * V_ * KP_HID, KP_HID, 0,
          out + (long)s * BATCH * V_, V_, 0, nullptr, 0, pred_b + (long)s * V_, 0,
          nullptr, 0, 0, BATCH, V_, KP_HID, 0, 1);
    }
}

// round 6
// speedup vs baseline: 3.5581x; 1.3928x over previous
#include <cuda_runtime.h>
#include <cuda_fp16.h>
#include <cstdint>

// ---------------------------------------------------------------------------
// Problem constants
// ---------------------------------------------------------------------------
#define S_   7
#define BATCH 8192
#define D_   1024
#define E_   256
#define H_   512
#define SH_  256
#define V_   100
#define D0_  1280
#define H4_  2048

typedef __half half_t;

// Packed K' = 2K (A split hi/lo; B duplicated hi/hi)
#define C0K  1536   // cat0: [emb 256 | h0 512] -> 768*2
#define C1K  2048   // cat1: [cur 512 | h1 512] -> 1024*2
#define DK   2048   // inputs D=1024 -> 2048
#define H1K  1024   // h1 512 -> 1024
#define HIDK 512    // hidden 256 -> 512

// ---------------------------------------------------------------------------
// Device scratch
// ---------------------------------------------------------------------------
__device__ float g_P_ih0[S_ * BATCH * H4_];      // interleaved gate cols, bias folded
__device__ float g_P_NL [S_ * BATCH * 1024];     // interleaved [N_j,L_j], bias folded
__device__ half_t g_Wcat0[S_ * H4_ * C0K];
__device__ half_t g_Wcat1[S_ * H4_ * C1K];
__device__ half_t g_WihD [S_ * H4_ * DK];
__device__ half_t g_WNLD [S_ * 1024 * DK];
__device__ half_t g_WNL  [S_ * 1024 * C0K];
__device__ half_t g_SHW  [S_ * SH_ * H1K];
__device__ half_t g_PW   [S_ * V_ * HIDK];
__device__ half_t g_INP  [BATCH * DK];
__device__ half_t g_cat0A[2 * BATCH * C0K];      // double buffered
__device__ half_t g_cat0N[BATCH * C0K];
__device__ half_t g_cat1 [2 * BATCH * C1K];      // double buffered
__device__ half_t g_h1p  [2 * BATCH * H1K];
__device__ half_t g_hid  [2 * BATCH * HIDK];
__device__ float g_h0[BATCH * H_], g_c0[BATCH * H_], g_c1[BATCH * H_];
__device__ float g_bias0[S_ * H4_], g_bias1[S_ * H4_], g_biasNL[S_ * 1024];

// ---------------------------------------------------------------------------
// PTX helpers
// ---------------------------------------------------------------------------
__device__ __forceinline__ uint32_t smem_u32(const void* p) {
    uint32_t a;
    asm("{ .reg .u64 t; cvta.to.shared.u64 t, %1; cvt.u32.u64 %0, t; }" : "=r"(a) : "l"(p));
    return a;
}
__device__ __forceinline__ uint32_t sw128(uint32_t off) { return off ^ ((off >> 3) & 0x70); }
__device__ __forceinline__ void cpa16(uint32_t dst, const void* src, int sz) {
    asm volatile("cp.async.cg.shared.global [%0], [%1], 16, %2;"
                 :: "r"(dst), "l"(src), "r"(sz) : "memory");
}
__device__ __forceinline__ void ldsm4(uint32_t* r, uint32_t addr) {
    asm volatile("ldmatrix.sync.aligned.m8n8.x4.shared.b16 {%0,%1,%2,%3}, [%4];"
                 : "=r"(r[0]), "=r"(r[1]), "=r"(r[2]), "=r"(r[3]) : "r"(addr));
}
#define MMA_F16(cc, a0, a1, a2, a3, b0, b1)                                    \
    asm volatile("mma.sync.aligned.m16n8k16.row.col.f32.f16.f16.f32 "          \
                 "{%0,%1,%2,%3}, {%4,%5,%6,%7}, {%8,%9}, {%0,%1,%2,%3};\n"     \
                 : "+f"(cc[0]), "+f"(cc[1]), "+f"(cc[2]), "+f"(cc[3])          \
                 : "r"(a0), "r"(a1), "r"(a2), "r"(a3), "r"(b0), "r"(b1))

__device__ __forceinline__ float sigm(float x) { return 1.f / (1.f + __expf(-x)); }

// ---------------------------------------------------------------------------
// Generic packer: fp32 slice -> fp16 (hi at colOff, second copy at +off2:
// secondLo ? residual-lo : duplicate-hi). Row remap for gate interleaving:
//   srcRow = (r/rps)*sDrps + sDro + (r%rps)
//   dstRow = (r/rps)*dDrps + dDro + (r%rps)*dRmul
// ---------------------------------------------------------------------------
__global__ void conv_pack(const float* __restrict__ src, long srcLd, long srcColOff,
                          long sDrps, long sDro,
                          half_t* __restrict__ dst, long dstLd, long dstColOff,
                          long dDrps, long dDro, int dRmul,
                          int off2, int secondLo,
                          long rows, int cols, long rps)
{
    int c4n = cols >> 2;
    long total = rows * c4n;
    long stride = (long)gridDim.x * blockDim.x;
    for (long t = blockIdx.x * (long)blockDim.x + threadIdx.x; t < total; t += stride) {
        long r = t / c4n;
        int  cI = (int)(t - r * c4n) << 2;
        long rq = r / rps, rr = r - rq * rps;
        long srow = rq * sDrps + sDro + rr;
        long drow = rq * dDrps + dDro + rr * (long)dRmul;
        float4 v = *reinterpret_cast<const float4*>(src + srow * srcLd + srcColOff + cI);
        half_t h0 = __float2half(v.x), h1 = __float2half(v.y);
        half_t h2 = __float2half(v.z), h3 = __float2half(v.w);
        long base = drow * dstLd + dstColOff + cI;
        __half2* p = (__half2*)(dst + base);
        p[0] = __halves2half2(h0, h1);
        p[1] = __halves2half2(h2, h3);
        __half2* q = (__half2*)(dst + base + off2);
        if (secondLo) {
            half_t l0 = __float2half(v.x - __half2float(h0));
            half_t l1 = __float2half(v.y - __half2float(h1));
            half_t l2 = __float2half(v.z - __half2float(h2));
            half_t l3 = __float2half(v.w - __half2float(h3));
            q[0] = __halves2half2(l0, l1);
            q[1] = __halves2half2(l2, l3);
        } else {
            q[0] = __halves2half2(h0, h1);
            q[1] = __halves2half2(h2, h3);
        }
    }
}

__global__ void misc_init(const float* __restrict__ b_ih0, const float* __restrict__ b_hh0,
                          const float* __restrict__ b_ih1, const float* __restrict__ b_hh1,
                          const float* __restrict__ hwN_b0)
{
    long stride = (long)gridDim.x * blockDim.x;
    long i0 = blockIdx.x * (long)blockDim.x + threadIdx.x;
    for (long t = i0; t < S_ * H4_; t += stride) {
        long s = t / H4_, n = t % H4_;
        long j = n >> 2, g = n & 3;
        long src = s * H4_ + g * H_ + j;
        g_bias0[t] = b_ih0[src] + b_hh0[src];
        g_bias1[t] = b_ih1[src] + b_hh1[src];
    }
    for (long t = i0; t < S_ * 1024; t += stride) {
        long s = t / 1024, n = t % 1024;
        g_biasNL[t] = (n & 1) ? 0.f : hwN_b0[s * H_ + (n >> 1)];
    }
}

// cur_emb -> cat0A[p] and cat0N (hi + lo)
__global__ void build_cat0_emb(const float* __restrict__ start,
                               const float* __restrict__ emb,
                               const int* __restrict__ labels, int s,
                               half_t* __restrict__ dA, half_t* __restrict__ dN)
{
    int idx = blockIdx.x * blockDim.x + threadIdx.x;
    if (idx >= BATCH * E_) return;
    int b = idx / E_, e = idx % E_;
    float v;
    if (s == 0) v = start[e];
    else {
        int lab = labels[(s - 1) * BATCH + b];
        v = emb[((long)(s - 1) * V_ + lab) * E_ + e];
    }
    half_t hh = __float2half(v);
    half_t hl = __float2half(v - __half2float(hh));
    long o = (long)b * C0K + e;
    dA[o] = hh; dA[o + 768] = hl;
    dN[o] = hh; dN[o + 768] = hl;
}

// ---------------------------------------------------------------------------
// fp16 NT GEMM with fused epilogues.
// modes: 0 = fp32 C (+bias,+Cin,relu); 1 = packed fp16 out (sh->hid, relu);
//        2 = LSTM0 (Cin, state c0, writes h0 + cat0 packed);
//        3 = HWY  (Cin, reads h0, writes cat1 cur packed);
//        4 = LSTM1 (bias, state c1, writes cat1 h + h1p packed).
// Gate-interleaved N layout for modes 2/4 (n=4j+g), pair-interleave mode 3.
// ---------------------------------------------------------------------------
#define BM 128
#define BN 128
#define BK 64
#define STG_BYTES 16384
#define SMEM_GEMM (6 * STG_BYTES)

__global__ __launch_bounds__(256, 2)
void gemm_mma(const half_t* __restrict__ A, int lda, long sA,
              const half_t* __restrict__ B, int ldb, long sB,
              float* __restrict__ C, int ldc, long sC,
              const float* __restrict__ Cin, long sCin,
              const float* __restrict__ bias, long sBias,
              half_t* __restrict__ O1, half_t* __restrict__ O2,
              float* __restrict__ X1, float* __restrict__ X2,
              int M, int N, int K, int mode, int relu)
{
    extern __shared__ char smem[];
    const uint32_t sbA = smem_u32(smem);
    const uint32_t sbB = sbA + 3 * STG_BYTES;

    const int z = blockIdx.z;
    A += z * sA;  B += z * sB;
    if (C)    C    += z * sC;
    if (Cin)  Cin  += z * sCin;
    if (bias) bias += z * sBias;

    const int tid = threadIdx.x;
    const int warp = tid >> 5, lane = tid & 31;
    const int m0 = blockIdx.y * BM, n0 = blockIdx.x * BN;
    const int wm = (warp & 1) * 64, wn = (warp >> 1) * 32;

    float c[4][4][4];
#pragma unroll
    for (int i = 0; i < 4; ++i)
#pragma unroll
        for (int j = 0; j < 4; ++j)
#pragma unroll
            for (int r = 0; r < 4; ++r) c[i][j][r] = 0.f;

    const int kT = K / BK;

    auto issue = [&](int t) {
        const int kk = t * BK;
        const uint32_t aBuf = sbA + (t % 3) * STG_BYTES;
        const uint32_t bBuf = sbB + (t % 3) * STG_BYTES;
#pragma unroll
        for (int w = 0; w < 4; ++w) {
            int g = tid + w * 256;
            int row = g >> 3, q = g & 7;
            const char* srcA = (const char*)(A + (long)(m0 + row) * lda + kk) + q * 16;
            cpa16(aBuf + sw128(row * 128 + q * 16), srcA, 16);
        }
#pragma unroll
        for (int w = 0; w < 4; ++w) {
            int g = tid + w * 256;
            int row = g >> 3, q = g & 7;
            int n = n0 + row;
            const char* srcB = (const char*)(B + (long)n * ldb + kk) + q * 16;
            cpa16(bBuf + sw128(row * 128 + q * 16), (n < N) ? srcB : (const char*)B,
                  (n < N) ? 16 : 0);
        }
        asm volatile("cp.async.commit_group;" ::: "memory");
    };

    issue(0);
    if (kT > 1) issue(1);

    for (int t = 0; t < kT; ++t) {
        if (t + 1 < kT) asm volatile("cp.async.wait_group 1;" ::: "memory");
        else            asm volatile("cp.async.wait_group 0;" ::: "memory");
        __syncthreads();
        if (t + 2 < kT) issue(t + 2);

        const uint32_t aS = sbA + (t % 3) * STG_BYTES;
        const uint32_t bS = sbB + (t % 3) * STG_BYTES;
#pragma unroll
        for (int ks = 0; ks < 4; ++ks) {
            uint32_t a[4][4], b[2][4];
            const int colByte = (ks * 16 + ((lane >> 4) << 3)) * 2;
#pragma unroll
            for (int i = 0; i < 4; ++i)
                ldsm4(a[i], aS + sw128((wm + i * 16 + (lane & 15)) * 128 + colByte));
#pragma unroll
            for (int jb = 0; jb < 2; ++jb)
                ldsm4(b[jb], bS + sw128((wn + jb * 16 + (lane & 15)) * 128 + colByte));
#pragma unroll
            for (int i = 0; i < 4; ++i)
#pragma unroll
                for (int j = 0; j < 4; ++j) {
                    const int jb = j >> 1, sel = j & 1;
                    MMA_F16(c[i][j], a[i][0], a[i][1], a[i][2], a[i][3],
                            b[jb][sel], b[jb][sel + 2]);
                }
        }
    }

    if (mode <= 1) {
        // fragment-direct epilogue
#pragma unroll
        for (int i = 0; i < 4; ++i) {
#pragma unroll
            for (int rr = 0; rr < 2; ++rr) {
                const int m = m0 + wm + i * 16 + (lane >> 2) + rr * 8;
#pragma unroll
                for (int j = 0; j < 4; ++j) {
                    const int n = n0 + wn + j * 8 + (lane & 3) * 2;
                    if (n < N) {
                        float v0 = c[i][j][rr * 2 + 0];
                        float v1 = c[i][j][rr * 2 + 1];
                        if (bias) { v0 += bias[n]; v1 += bias[n + 1]; }
                        const long idx = (long)m * ldc + n;
                        if (Cin) { v0 += Cin[idx]; v1 += Cin[idx + 1]; }
                        if (relu) { v0 = fmaxf(v0, 0.f); v1 = fmaxf(v1, 0.f); }
                        if (mode == 1) {
                            // packed split out, ld=HIDK, lo at +256
                            const long o = (long)m * HIDK + n;
                            half_t h0 = __float2half(v0), h1 = __float2half(v1);
                            half_t l0 = __float2half(v0 - __half2float(h0));
                            half_t l1 = __float2half(v1 - __half2float(h1));
                            *(__half2*)(O1 + o)       = __halves2half2(h0, h1);
                            *(__half2*)(O1 + o + 256) = __halves2half2(l0, l1);
                        } else {
                            float2 st; st.x = v0; st.y = v1;
                            *(float2*)(C + idx) = st;
                        }
                    }
                }
            }
        }
    } else {
        // stage accumulators to smem, then consume in LSTM/HWY layout
        __syncthreads();
        float* sAcc = (float*)smem;
#pragma unroll
        for (int i = 0; i < 4; ++i)
#pragma unroll
            for (int j = 0; j < 4; ++j)
#pragma unroll
                for (int rr = 0; rr < 2; ++rr)
#pragma unroll
                    for (int cc = 0; cc < 2; ++cc)
                        sAcc[(wm + i * 16 + (lane >> 2) + rr * 8) * 132 +
                             wn + j * 8 + (lane & 3) * 2 + cc] = c[i][j][rr * 2 + cc];
        __syncthreads();

        if (mode == 2 || mode == 4) {
            const int jbase = n0 >> 2;
            for (int t = tid; t < 128 * 32; t += 256) {
                const int row = t >> 5, jj = t & 31;
                const int b = m0 + row, j = jbase + jj;
                float gv[4];
#pragma unroll
                for (int g = 0; g < 4; ++g) {
                    float x = sAcc[row * 132 + 4 * jj + g];
                    if (mode == 2) x += Cin[(long)b * ldc + n0 + 4 * jj + g];
                    else           x += bias[n0 + 4 * jj + g];
                    gv[g] = x;
                }
                const float ig = sigm(gv[0]), fg = sigm(gv[1]);
                const float gg = tanhf(gv[2]), og = sigm(gv[3]);
                const long sidx = (long)b * H_ + j;
                const float cn = fg * X1[sidx] + ig * gg;
                const float hn = og * tanhf(cn);
                X1[sidx] = cn;
                half_t hh = __float2half(hn);
                half_t hl = __float2half(hn - __half2float(hh));
                if (mode == 2) {
                    X2[sidx] = hn;
                    const long o = (long)b * C0K + 256 + j;
                    O1[o] = hh; O1[o + 768] = hl;
                    O2[o] = hh; O2[o + 768] = hl;
                } else {
                    const long o1 = (long)b * C1K + 512 + j;
                    O1[o1] = hh; O1[o1 + 1024] = hl;
                    const long o2 = (long)b * H1K + j;
                    O2[o2] = hh; O2[o2 + 512] = hl;
                }
            }
        } else {  // mode 3: highway
            const int jbase = n0 >> 1;
            for (int t = tid; t < 128 * 64; t += 256) {
                const int row = t >> 6, jj = t & 63;
                const int b = m0 + row, j = jbase + jj;
                const float gN = sAcc[row * 132 + 2 * jj] +
                                 Cin[(long)b * ldc + n0 + 2 * jj];
                const float lv = sAcc[row * 132 + 2 * jj + 1] +
                                 Cin[(long)b * ldc + n0 + 2 * jj + 1];
                const float sg = sigm(gN);
                const float cur = sg * X1[(long)b * H_ + j] + (1.f - sg) * lv;
                half_t hh = __float2half(cur);
                half_t hl = __float2half(cur - __half2float(hh));
                const long o = (long)b * C1K + j;
                O1[o] = hh; O1[o + 1024] = hl;
            }
        }
    }
}

// ---------------------------------------------------------------------------
// Host
// ---------------------------------------------------------------------------
#define SYM(var, sym) cudaGetSymbolAddress((void**)&var, sym)

static inline void G(const half_t* A, int lda, long sA,
                     const half_t* B, int ldb, long sB,
                     float* C, int ldc, long sC,
                     const float* Cin, long sCin,
                     const float* bias, long sBias,
                     half_t* O1, half_t* O2, float* X1, float* X2,
                     int M, int N, int K, int mode, int relu, int Z,
                     cudaStream_t st)
{
    dim3 grid((N + BN - 1) / BN, M / BM, Z);
    gemm_mma<<<grid, 256, SMEM_GEMM, st>>>(A, lda, sA, B, ldb, sB, C, ldc, sC,
                                           Cin, sCin, bias, sBias, O1, O2, X1, X2,
                                           M, N, K, mode, relu);
}

extern "C" void kernel_launch(void* const* d_in, const int* in_sizes, int n_in,
                              void* d_out, int out_size)
{
    const float* inputs = (const float*)d_in[0];
    const int*   labels = (const int*)  d_in[1];
    const float* start  = (const float*)d_in[2];
    const float* emb    = (const float*)d_in[3];
    const float* W_ih0  = (const float*)d_in[4];
    const float* W_hh0  = (const float*)d_in[5];
    const float* b_ih0  = (const float*)d_in[6];
    const float* b_hh0  = (const float*)d_in[7];
    const float* hwN_W0 = (const float*)d_in[8];
    const float* hwN_b0 = (const float*)d_in[9];
    const float* hwL_W0 = (const float*)d_in[10];
    const float* W_ih1  = (const float*)d_in[11];
    const float* W_hh1  = (const float*)d_in[12];
    const float* b_ih1  = (const float*)d_in[13];
    const float* b_hh1  = (const float*)d_in[14];
    // d_in[15..17] dead in reference (layer-1 highway output unused)
    const float* sh_W   = (const float*)d_in[18];
    const float* sh_b   = (const float*)d_in[19];
    const float* pred_W = (const float*)d_in[20];
    const float* pred_b = (const float*)d_in[21];
    float* out = (float*)d_out;

    static cudaStream_t side = nullptr;
    static cudaEvent_t evM[S_], evS[S_];
    if (!side) {
        cudaStreamCreateWithFlags(&side, cudaStreamNonBlocking);
        for (int i = 0; i < S_; ++i) {
            cudaEventCreateWithFlags(&evM[i], cudaEventDisableTiming);
            cudaEventCreateWithFlags(&evS[i], cudaEventDisableTiming);
        }
        cudaFuncSetAttribute(gemm_mma, cudaFuncAttributeMaxDynamicSharedMemorySize,
                             SMEM_GEMM);
    }

    float *P_ih0, *P_NL, *bias0, *bias1, *biasNL, *h0, *c0, *c1;
    half_t *Wcat0, *Wcat1, *WihD, *WNLD, *WNL, *SHW, *PW, *INP;
    half_t *cat0A, *cat0N, *cat1, *h1p, *hid;
    SYM(P_ih0, g_P_ih0); SYM(P_NL, g_P_NL);
    SYM(bias0, g_bias0); SYM(bias1, g_bias1); SYM(biasNL, g_biasNL);
    SYM(h0, g_h0); SYM(c0, g_c0); SYM(c1, g_c1);
    SYM(Wcat0, g_Wcat0); SYM(Wcat1, g_Wcat1); SYM(WihD, g_WihD);
    SYM(WNLD, g_WNLD); SYM(WNL, g_WNL); SYM(SHW, g_SHW); SYM(PW, g_PW);
    SYM(INP, g_INP);
    SYM(cat0A, g_cat0A); SYM(cat0N, g_cat0N); SYM(cat1, g_cat1);
    SYM(h1p, g_h1p); SYM(hid, g_hid);

    half_t* cat0Ab[2] = { cat0A, cat0A + (long)BATCH * C0K };
    half_t* cat1b [2] = { cat1,  cat1  + (long)BATCH * C1K };
    half_t* h1pb  [2] = { h1p,   h1p   + (long)BATCH * H1K };
    half_t* hidb  [2] = { hid,   hid   + (long)BATCH * HIDK };

    // ---- init: zero states + recurrent slices + WNL padding ----
    cudaMemsetAsync(c0, 0, (long)BATCH * H_ * 4);
    cudaMemsetAsync(c1, 0, (long)BATCH * H_ * 4);
    cudaMemsetAsync(cat0A, 0, 2L * BATCH * C0K * 2);
    cudaMemsetAsync(cat1,  0, 2L * BATCH * C1K * 2);
    cudaMemsetAsync(WNL,   0, (long)S_ * 1024 * C0K * 2);

    // ---- pack weights (gate-interleaved where fused) ----
    const int CB = 2048;
    const long BIGR = 1L << 40;
    for (int g = 0; g < 4; ++g) {
        // Wcat0: emb cols of W_ih0 + W_hh0, rows -> 4j+g
        conv_pack<<<CB, 256>>>(W_ih0, D0_, D_, H4_, (long)g * H_,
                               Wcat0, C0K, 0, H4_, g, 4, 768, 0,
                               (long)S_ * H_, E_, H_);
        conv_pack<<<CB, 256>>>(W_hh0, H_, 0, H4_, (long)g * H_,
                               Wcat0, C0K, E_, H4_, g, 4, 768, 0,
                               (long)S_ * H_, H_, H_);
        // Wcat1
        conv_pack<<<CB, 256>>>(W_ih1, H_, 0, H4_, (long)g * H_,
                               Wcat1, C1K, 0, H4_, g, 4, 1024, 0,
                               (long)S_ * H_, H_, H_);
        conv_pack<<<CB, 256>>>(W_hh1, H_, 0, H4_, (long)g * H_,
                               Wcat1, C1K, H_, H4_, g, 4, 1024, 0,
                               (long)S_ * H_, H_, H_);
        // WihD: W_ih0[:, :D] interleaved
        conv_pack<<<CB, 256>>>(W_ih0, D0_, 0, H4_, (long)g * H_,
                               WihD, DK, 0, H4_, g, 4, 1024, 0,
                               (long)S_ * H_, D_, H_);
    }
    // WNLD: pair-interleaved [N_j, L_j], D-cols
    conv_pack<<<CB, 256>>>(hwN_W0, D0_ + H_, 0, H_, 0,
                           WNLD, DK, 0, 1024, 0, 2, 1024, 0,
                           (long)S_ * H_, D_, H_);
    conv_pack<<<CB, 256>>>(hwL_W0, D0_, 0, H_, 0,
                           WNLD, DK, 0, 1024, 1, 2, 1024, 0,
                           (long)S_ * H_, D_, H_);
    // WNL: pair-interleaved recurrent cols (hwN 768 cols; hwL 256 cols, rest zero)
    conv_pack<<<CB, 256>>>(hwN_W0, D0_ + H_, D_, H_, 0,
                           WNL, C0K, 0, 1024, 0, 2, 768, 0,
                           (long)S_ * H_, E_ + H_, H_);
    conv_pack<<<CB, 256>>>(hwL_W0, D0_, D_, H_, 0,
                           WNL, C0K, 0, 1024, 1, 2, 768, 0,
                           (long)S_ * H_, E_, H_);
    // SHW / PW plain
    conv_pack<<<CB, 256>>>(sh_W, H_, 0, 0, 0,
                           SHW, H1K, 0, 0, 0, 1, 512, 0,
                           (long)S_ * SH_, H_, BIGR);
    conv_pack<<<CB, 256>>>(pred_W, SH_, 0, 0, 0,
                           PW, HIDK, 0, 0, 0, 1, 256, 0,
                           (long)S_ * V_, SH_, BIGR);
    // INP: A-side split hi/lo
    conv_pack<<<CB, 256>>>(inputs, D_, 0, 0, 0,
                           INP, DK, 0, 0, 0, 1, 1024, 1,
                           (long)BATCH, D_, BIGR);
    misc_init<<<CB, 256>>>(b_ih0, b_hh0, b_ih1, b_hh1, hwN_b0);

    // ---- slot-parallel precompute (z = S), bias folded ----
    G(INP, DK, 0, WihD, DK, (long)H4_ * DK,
      P_ih0, H4_, (long)BATCH * H4_, nullptr, 0, bias0, H4_,
      nullptr, nullptr, nullptr, nullptr, BATCH, H4_, DK, 0, 0, S_, 0);
    G(INP, DK, 0, WNLD, DK, (long)1024 * DK,
      P_NL, 1024, (long)BATCH * 1024, nullptr, 0, biasNL, 1024,
      nullptr, nullptr, nullptr, nullptr, BATCH, 1024, DK, 0, 0, S_, 0);

    const int embB = (BATCH * E_ + 255) / 256;

    // ---- sequential slots (fused epilogues; sh+pred on side stream) ----
    for (int s = 0; s < S_; ++s) {
        const int p = s & 1;
        build_cat0_emb<<<embB, 256>>>(start, emb, labels, s, cat0Ab[p], cat0N);

        // gates0 + LSTM0 fused
        G(cat0Ab[p], C0K, 0, Wcat0 + (long)s * H4_ * C0K, C0K, 0,
          nullptr, H4_, 0, P_ih0 + (long)s * BATCH * H4_, 0, nullptr, 0,
          cat0Ab[1 - p], cat0N, c0, h0, BATCH, H4_, C0K, 2, 0, 1, 0);

        // [gateN|lin] + highway fused
        G(cat0N, C0K, 0, WNL + (long)s * 1024 * C0K, C0K, 0,
          nullptr, 1024, 0, P_NL + (long)s * BATCH * 1024, 0, nullptr, 0,
          cat1b[p], nullptr, h0, nullptr, BATCH, 1024, C0K, 3, 0, 1, 0);

        // gates1 + LSTM1 fused (wait for sh/pred of slot s-2: h1p reuse)
        if (s >= 2) cudaStreamWaitEvent(0, evS[s - 2], 0);
        G(cat1b[p], C1K, 0, Wcat1 + (long)s * H4_ * C1K, C1K, 0,
          nullptr, H4_, 0, nullptr, 0, bias1 + (long)s * H4_, 0,
          cat1b[1 - p], h1pb[p], c1, nullptr, BATCH, H4_, C1K, 4, 0, 1, 0);

        cudaEventRecord(evM[s], 0);
        cudaStreamWaitEvent(side, evM[s], 0);

        // hidden = relu(h1 @ sh_W.T + sh_b) -> packed fp16 (side stream)
        G(h1pb[p], H1K, 0, SHW + (long)s * SH_ * H1K, H1K, 0,
          nullptr, HIDK, 0, nullptr, 0, sh_b + (long)s * SH_, 0,
          hidb[p], nullptr, nullptr, nullptr, BATCH, SH_, H1K, 1, 1, 1, side);

        // logits (side stream)
        G(hidb[p], HIDK, 0, PW + (long)s * V_ * HIDK, HIDK, 0,
          out + (long)s * BATCH * V_, V_, 0, nullptr, 0, pred_b + (long)s * V_, 0,
          nullptr, nullptr, nullptr, nullptr, BATCH, V_, HIDK, 0, 0, 1, side);

        cudaEventRecord(evS[s], side);
    }
    cudaStreamWaitEvent(0, evS[S_ - 2], 0);
    cudaStreamWaitEvent(0, evS[S_ - 1], 0);
}